// round 1
// baseline (speedup 1.0000x reference)
#include <cuda_runtime.h>
#include <math.h>

#define BN   1024
#define NV   6890
#define NJ   24
#define NBETA 10
#define NP   207
#define NK   19
#define INW  82      // inputs row width: 72 pose + 10 shape

// ---- scratch (device globals; no allocation allowed) ----
__device__ float g_Jdirs[NBETA * NJ * 3];   // [n][k*3+c]
__device__ float g_Jtmpl[NJ * 3];
__device__ float g_jregT[NK * NV];          // transposed joint_regressor
__device__ float g_pf[BN * NP];             // pose features
__device__ float g_relA[BN * NJ * 12];      // per-batch 3x4 skinning transforms

__constant__ int c_parents[NJ] = {0,0,0,0,1,2,3,4,5,6,7,8,9,9,9,12,13,14,16,17,18,19,20,21};

// =====================================================================
// K0a: fold smpl_j_regressor into shapedirs/template ->
//      J_dirs[n][k][c] = sum_v shapedirs[n, v*3+c] * reg[v,k]
//      J_tmpl[k][c]    = sum_v tmpl[v,c] * reg[v,k]
// grid = 72 (k*3+c), block = 256
// =====================================================================
__global__ void k0a_jointdirs(const float* __restrict__ tmpl,
                              const float* __restrict__ sdirs,
                              const float* __restrict__ jreg)
{
    int k = blockIdx.x / 3, c = blockIdx.x % 3;
    float acc[NBETA + 1];
#pragma unroll
    for (int t = 0; t <= NBETA; t++) acc[t] = 0.f;

    for (int v = threadIdx.x; v < NV; v += 256) {
        float r = jreg[v * NJ + k];
        acc[0] += tmpl[v * 3 + c] * r;
#pragma unroll
        for (int n = 0; n < NBETA; n++)
            acc[1 + n] += sdirs[n * (NV * 3) + v * 3 + c] * r;
    }
    __shared__ float red[256];
    for (int t = 0; t <= NBETA; t++) {
        __syncthreads();
        red[threadIdx.x] = acc[t];
        __syncthreads();
        for (int s = 128; s > 0; s >>= 1) {
            if (threadIdx.x < s) red[threadIdx.x] += red[threadIdx.x + s];
            __syncthreads();
        }
        if (threadIdx.x == 0) {
            if (t == 0) g_Jtmpl[k * 3 + c] = red[0];
            else        g_Jdirs[(t - 1) * (NJ * 3) + k * 3 + c] = red[0];
        }
    }
}

// K0b: transpose joint_regressor [V,19] -> [19,V]
__global__ void k0b_transpose(const float* __restrict__ jr)
{
    int idx = blockIdx.x * blockDim.x + threadIdx.x;
    if (idx < NV * NK) {
        int v = idx / NK, k = idx % NK;
        g_jregT[k * NV + v] = jr[idx];
    }
}

// =====================================================================
// K1: per-batch — rotations, pose features, joints, kinematic chain, rel_A
// grid = B, block = 128
// =====================================================================
__global__ void k1_batchprep(const float* __restrict__ inputs,
                             float* __restrict__ outRs)
{
    int b = blockIdx.x;
    int tid = threadIdx.x;
    __shared__ float sR[NJ][9];
    __shared__ float sJ[NJ][3];
    __shared__ float sG[NJ][12];

    // Rodrigues
    if (tid < NJ) {
        const float* aa = inputs + (size_t)b * INW + tid * 3;
        float x = aa[0], y = aa[1], z = aa[2];
        float ang = sqrtf(x * x + y * y + z * z + 1e-8f);
        float inv = 1.f / ang;
        x *= inv; y *= inv; z *= inv;
        float cc = cosf(ang), ss = sinf(ang), C = 1.f - cc;
        float R[9];
        R[0] = cc + C * x * x;   R[1] = C * x * y - ss * z; R[2] = C * x * z + ss * y;
        R[3] = C * x * y + ss * z; R[4] = cc + C * y * y;   R[5] = C * y * z - ss * x;
        R[6] = C * x * z - ss * y; R[7] = C * y * z + ss * x; R[8] = cc + C * z * z;
#pragma unroll
        for (int e = 0; e < 9; e++) {
            sR[tid][e] = R[e];
            outRs[(size_t)b * (NJ * 9) + tid * 9 + e] = R[e];
        }
    }
    __syncthreads();

    // pose_feature = (Rs[1:] - I).reshape(207)
    for (int idx = tid; idx < NP; idx += 128) {
        int j = 1 + idx / 9, e = idx % 9;
        float d = (e == 0 || e == 4 || e == 8) ? 1.f : 0.f;
        g_pf[(size_t)b * NP + idx] = sR[j][e] - d;
    }

    // v_joints via folded regressor
    if (tid < NJ) {
        const float* shp = inputs + (size_t)b * INW + 72;
#pragma unroll
        for (int c = 0; c < 3; c++) {
            float v = g_Jtmpl[tid * 3 + c];
#pragma unroll
            for (int n = 0; n < NBETA; n++)
                v += shp[n] * g_Jdirs[n * (NJ * 3) + tid * 3 + c];
            sJ[tid][c] = v;
        }
    }
    __syncthreads();

    // kinematic chain: 12 threads compute one 3x4 element each, serial over joints
    if (tid < 12) {
        int r = tid / 4, col = tid % 4;
        sG[0][r * 4 + col] = (col < 3) ? sR[0][r * 3 + col] : sJ[0][r];
        for (int i = 1; i < NJ; i++) {
            __syncwarp(0xFFFu);
            int p = c_parents[i];
            float v;
            if (col < 3) {
                v = sG[p][r * 4 + 0] * sR[i][0 * 3 + col]
                  + sG[p][r * 4 + 1] * sR[i][1 * 3 + col]
                  + sG[p][r * 4 + 2] * sR[i][2 * 3 + col];
            } else {
                float t0 = sJ[i][0] - sJ[p][0];
                float t1 = sJ[i][1] - sJ[p][1];
                float t2 = sJ[i][2] - sJ[p][2];
                v = sG[p][r * 4 + 0] * t0 + sG[p][r * 4 + 1] * t1
                  + sG[p][r * 4 + 2] * t2 + sG[p][r * 4 + 3];
            }
            sG[i][r * 4 + col] = v;
        }
        __syncwarp(0xFFFu);
    }
    __syncthreads();

    // rel_A = G with translation t - R*J
    for (int idx = tid; idx < NJ * 12; idx += 128) {
        int j = idx / 12, rc = idx % 12, r = rc / 4, col = rc % 4;
        float v;
        if (col < 3) v = sG[j][r * 4 + col];
        else v = sG[j][r * 4 + 3]
               - (sG[j][r * 4 + 0] * sJ[j][0] + sG[j][r * 4 + 1] * sJ[j][1]
                + sG[j][r * 4 + 2] * sJ[j][2]);
        g_relA[(size_t)b * (NJ * 12) + idx] = v;
    }
}

// =====================================================================
// K2: main fused kernel: v_shaped + pose blend + LBS -> vertices
// tile: BT=32 batches x VT=64 vertices, 256 threads, reg tile 4b x 2v
// =====================================================================
#define BT 32
#define VT 64
#define KC 23   // 207 = 9 * 23
#define K2_SMEM_FLOATS (BT*208 + BT*288 + NJ*VT + KC*3*VT + BT*NBETA + NBETA*3*VT + 3*VT)

__global__ void __launch_bounds__(256, 2)
k2_main(const float* __restrict__ inputs,
        const float* __restrict__ tmpl,
        const float* __restrict__ sdirs,
        const float* __restrict__ pdirs,
        const float* __restrict__ lbs,
        float* __restrict__ outV)
{
    extern __shared__ float smem[];
    float* s_pf    = smem;                    // [BT][208]
    float* s_relA  = s_pf    + BT * 208;      // [BT][288]
    float* s_lbsT  = s_relA  + BT * 288;      // [24][VT]
    float* s_pd    = s_lbsT  + NJ * VT;       // [KC][3][VT]
    float* s_shape = s_pd    + KC * 3 * VT;   // [BT][10]
    float* s_sd    = s_shape + BT * NBETA;    // [10][3][VT]
    float* s_tmpl  = s_sd    + NBETA * 3 * VT;// [3][VT]

    int tid = threadIdx.x;
    int b0 = blockIdx.y * BT;
    int v0 = blockIdx.x * VT;

    for (int idx = tid; idx < BT * NP; idx += 256) {
        int r = idx / NP, k = idx % NP;
        s_pf[r * 208 + k] = g_pf[(size_t)(b0 + r) * NP + k];
    }
    for (int idx = tid; idx < BT * 288; idx += 256)
        s_relA[idx] = g_relA[(size_t)b0 * 288 + idx];
    for (int idx = tid; idx < BT * NBETA; idx += 256) {
        int r = idx / NBETA, n = idx % NBETA;
        s_shape[idx] = inputs[(size_t)(b0 + r) * INW + 72 + n];
    }
    for (int idx = tid; idx < NJ * VT; idx += 256) {
        int j = idx / VT, vl = idx % VT, v = v0 + vl;
        s_lbsT[idx] = (v < NV) ? lbs[v * NJ + j] : 0.f;
    }
    for (int idx = tid; idx < 3 * VT; idx += 256) {
        int c = idx / VT, vl = idx % VT, v = v0 + vl;
        s_tmpl[idx] = (v < NV) ? tmpl[v * 3 + c] : 0.f;
    }
    for (int idx = tid; idx < NBETA * 3 * VT; idx += 256) {
        int n = idx / (3 * VT), t = idx % (3 * VT);
        int vl = t / 3, c = t % 3, v = v0 + vl;
        s_sd[(n * 3 + c) * VT + vl] = (v < NV) ? sdirs[n * (NV * 3) + v * 3 + c] : 0.f;
    }
    __syncthreads();

    int bg = tid >> 5, vg = tid & 31;

    // base: template + shape blend
    float acc[4][2][3];
#pragma unroll
    for (int i = 0; i < 4; i++)
#pragma unroll
        for (int rv = 0; rv < 2; rv++) {
            int vl = vg + rv * 32;
#pragma unroll
            for (int c = 0; c < 3; c++) {
                float t = s_tmpl[c * VT + vl];
#pragma unroll
                for (int n = 0; n < NBETA; n++)
                    t += s_shape[(bg * 4 + i) * NBETA + n] * s_sd[(n * 3 + c) * VT + vl];
                acc[i][rv][c] = t;
            }
        }

    // pose blend: 9 chunks of 23 K-steps
    int tmax = (NV - v0) * 3; if (tmax > 3 * VT) tmax = 3 * VT;
    for (int ch = 0; ch < 9; ch++) {
        __syncthreads();
        int kbase = ch * KC;
        for (int idx = tid; idx < KC * 3 * VT; idx += 256) {
            int kk = idx / (3 * VT), t = idx % (3 * VT);
            float val = (t < tmax) ? pdirs[(size_t)(kbase + kk) * (NV * 3) + (size_t)v0 * 3 + t] : 0.f;
            int vl = t / 3, c = t % 3;
            s_pd[(kk * 3 + c) * VT + vl] = val;
        }
        __syncthreads();
#pragma unroll
        for (int kk = 0; kk < KC; kk++) {
            float pfv[4];
#pragma unroll
            for (int i = 0; i < 4; i++)
                pfv[i] = s_pf[(bg * 4 + i) * 208 + kbase + kk];
            float pd[2][3];
#pragma unroll
            for (int rv = 0; rv < 2; rv++)
#pragma unroll
                for (int c = 0; c < 3; c++)
                    pd[rv][c] = s_pd[(kk * 3 + c) * VT + vg + rv * 32];
#pragma unroll
            for (int i = 0; i < 4; i++)
#pragma unroll
                for (int rv = 0; rv < 2; rv++)
#pragma unroll
                    for (int c = 0; c < 3; c++)
                        acc[i][rv][c] += pfv[i] * pd[rv][c];
        }
    }

    // LBS
    float o[4][2][3];
#pragma unroll
    for (int i = 0; i < 4; i++)
#pragma unroll
        for (int rv = 0; rv < 2; rv++)
#pragma unroll
            for (int c = 0; c < 3; c++) o[i][rv][c] = 0.f;

    for (int j = 0; j < NJ; j++) {
        float w0 = s_lbsT[j * VT + vg];
        float w1 = s_lbsT[j * VT + vg + 32];
#pragma unroll
        for (int i = 0; i < 4; i++) {
            const float* A = &s_relA[(bg * 4 + i) * 288 + j * 12];
            float a0 = A[0], a1 = A[1], a2 = A[2],  a3 = A[3];
            float a4 = A[4], a5 = A[5], a6 = A[6],  a7 = A[7];
            float a8 = A[8], a9 = A[9], a10 = A[10], a11 = A[11];
#pragma unroll
            for (int rv = 0; rv < 2; rv++) {
                float w = rv ? w1 : w0;
                float px = acc[i][rv][0], py = acc[i][rv][1], pz = acc[i][rv][2];
                o[i][rv][0] += w * (a0 * px + a1 * py + a2  * pz + a3);
                o[i][rv][1] += w * (a4 * px + a5 * py + a6  * pz + a7);
                o[i][rv][2] += w * (a8 * px + a9 * py + a10 * pz + a11);
            }
        }
    }

#pragma unroll
    for (int i = 0; i < 4; i++)
#pragma unroll
        for (int rv = 0; rv < 2; rv++) {
            int vl = vg + rv * 32, v = v0 + vl;
            if (v < NV) {
                size_t base = ((size_t)(b0 + bg * 4 + i) * NV + v) * 3;
#pragma unroll
                for (int c = 0; c < 3; c++)
                    outV[base + c] = o[i][rv][c];
            }
        }
}

// =====================================================================
// K3: joints = einsum('bvc,vk->bkc', vertices, joint_regressor)
// grid = B, block = 256, 57 accumulators/thread
// =====================================================================
__global__ void k3_joints(const float* __restrict__ verts,
                          float* __restrict__ outJ)
{
    int b = blockIdx.x, tid = threadIdx.x;
    float accj[NK * 3];
#pragma unroll
    for (int t = 0; t < NK * 3; t++) accj[t] = 0.f;

    for (int v = tid; v < NV; v += 256) {
        const float* p = &verts[((size_t)b * NV + v) * 3];
        float p0 = p[0], p1 = p[1], p2 = p[2];
#pragma unroll
        for (int k = 0; k < NK; k++) {
            float r = g_jregT[k * NV + v];
            accj[k * 3 + 0] += r * p0;
            accj[k * 3 + 1] += r * p1;
            accj[k * 3 + 2] += r * p2;
        }
    }
    __shared__ float sred[8][NK * 3];
    int lane = tid & 31, wid = tid >> 5;
#pragma unroll
    for (int t = 0; t < NK * 3; t++) {
        float val = accj[t];
#pragma unroll
        for (int off = 16; off > 0; off >>= 1)
            val += __shfl_down_sync(0xFFFFFFFFu, val, off);
        if (lane == 0) sred[wid][t] = val;
    }
    __syncthreads();
    if (tid < NK * 3) {
        float s = 0.f;
#pragma unroll
        for (int w = 0; w < 8; w++) s += sred[w][tid];
        outJ[(size_t)b * (NK * 3) + tid] = s;
    }
}

// =====================================================================
extern "C" void kernel_launch(void* const* d_in, const int* in_sizes, int n_in,
                              void* d_out, int out_size)
{
    const float* inputs = (const float*)d_in[0];
    const float* vtempl = (const float*)d_in[1];
    const float* sdirs  = (const float*)d_in[2];
    const float* jreg24 = (const float*)d_in[3];
    const float* pdirs  = (const float*)d_in[4];
    const float* lbsw   = (const float*)d_in[5];
    const float* jreg19 = (const float*)d_in[6];

    float* out   = (float*)d_out;
    float* outV  = out;                                   // [B,V,3]
    float* outJ  = outV + (size_t)BN * NV * 3;            // [B,19,3]
    float* outRs = outJ + (size_t)BN * NK * 3;            // [B,24,3,3]

    size_t k2_smem = (size_t)K2_SMEM_FLOATS * sizeof(float);
    cudaFuncSetAttribute(k2_main, cudaFuncAttributeMaxDynamicSharedMemorySize, (int)k2_smem);

    k0a_jointdirs<<<NJ * 3, 256>>>(vtempl, sdirs, jreg24);
    k0b_transpose<<<(NV * NK + 255) / 256, 256>>>(jreg19);
    k1_batchprep<<<BN, 128>>>(inputs, outRs);
    dim3 g2((NV + VT - 1) / VT, BN / BT);
    k2_main<<<g2, 256, k2_smem>>>(inputs, vtempl, sdirs, pdirs, lbsw, outV);
    k3_joints<<<BN, 256>>>(outV, outJ);
}

// round 4
// speedup vs baseline: 2.1530x; 2.1530x over previous
#include <cuda_runtime.h>
#include <math.h>
#include <stdint.h>

#define BN 1024
#define NV 6890
#define NV3 20670
#define NJ 24
#define NBETA 10
#define NP 207
#define NK 19
#define INW 82

#define BT 32      // batches per block
#define VT 128     // vertices per block
#define KC 23      // K-chunk of pose blend (9*23 = 207)
#define NCH 9

typedef unsigned long long u64;

// ---- scratch (device globals) ----
__device__ float g_Jdirs[NBETA * NJ * 3];
__device__ float g_Jtmpl[NJ * 3];
__device__ float g_jregT[NK * NV];
__device__ float g_lbsT[NJ * NV];
__device__ float g_pf[BN * NP];
__device__ __align__(16) float g_relA[BN * NJ * 12 * 2];   // duplicated pairs

__constant__ int c_parents[NJ] = {0,0,0,0,1,2,3,4,5,6,7,8,9,9,9,12,13,14,16,17,18,19,20,21};

// ---- packed f32x2 helpers ----
__device__ __forceinline__ u64 ffma2(u64 a, u64 b, u64 c) {
    u64 d;
    asm("fma.rn.f32x2 %0, %1, %2, %3;" : "=l"(d) : "l"(a), "l"(b), "l"(c));
    return d;
}
__device__ __forceinline__ u64 pack2(float a, float b) {
    u64 r;
    asm("mov.b64 %0, {%1, %2};" : "=l"(r) : "f"(a), "f"(b));
    return r;
}
__device__ __forceinline__ void unpk(u64 v, float& a, float& b) {
    asm("mov.b64 {%0, %1}, %2;" : "=f"(a), "=f"(b) : "l"(v));
}
union U4 { uint4 q; u64 h[2]; };

__device__ __forceinline__ unsigned su32(const void* p) {
    return (unsigned)__cvta_generic_to_shared(p);
}

// =====================================================================
// K0a: fold smpl_j_regressor into shapedirs/template
// =====================================================================
__global__ void k0a_jointdirs(const float* __restrict__ tmpl,
                              const float* __restrict__ sdirs,
                              const float* __restrict__ jreg)
{
    int k = blockIdx.x / 3, c = blockIdx.x % 3;
    float acc[NBETA + 1];
#pragma unroll
    for (int t = 0; t <= NBETA; t++) acc[t] = 0.f;

    for (int v = threadIdx.x; v < NV; v += 256) {
        float r = jreg[v * NJ + k];
        acc[0] += tmpl[v * 3 + c] * r;
#pragma unroll
        for (int n = 0; n < NBETA; n++)
            acc[1 + n] += sdirs[n * (NV * 3) + v * 3 + c] * r;
    }
    __shared__ float red[256];
    for (int t = 0; t <= NBETA; t++) {
        __syncthreads();
        red[threadIdx.x] = acc[t];
        __syncthreads();
        for (int s = 128; s > 0; s >>= 1) {
            if (threadIdx.x < s) red[threadIdx.x] += red[threadIdx.x + s];
            __syncthreads();
        }
        if (threadIdx.x == 0) {
            if (t == 0) g_Jtmpl[k * 3 + c] = red[0];
            else        g_Jdirs[(t - 1) * (NJ * 3) + k * 3 + c] = red[0];
        }
    }
}

// K0b: transpose joint_regressor [V,19] -> [19,V]
__global__ void k0b_transpose(const float* __restrict__ jr)
{
    int idx = blockIdx.x * blockDim.x + threadIdx.x;
    if (idx < NV * NK) {
        int v = idx / NK, k = idx % NK;
        g_jregT[k * NV + v] = jr[idx];
    }
}

// K0c: transpose lbs_weights [V,24] -> [24,V]
__global__ void k0c_lbsT(const float* __restrict__ lbs)
{
    int idx = blockIdx.x * blockDim.x + threadIdx.x;
    if (idx < NV * NJ) {
        int v = idx / NJ, j = idx - v * NJ;
        g_lbsT[j * NV + v] = lbs[idx];
    }
}

// =====================================================================
// K1: per-batch rotations, pose features, joints, kinematic chain, rel_A
// =====================================================================
__global__ void k1_batchprep(const float* __restrict__ inputs,
                             float* __restrict__ outRs)
{
    int b = blockIdx.x;
    int tid = threadIdx.x;
    __shared__ float sR[NJ][9];
    __shared__ float sJ[NJ][3];
    __shared__ float sG[NJ][12];

    if (tid < NJ) {
        const float* aa = inputs + (size_t)b * INW + tid * 3;
        float x = aa[0], y = aa[1], z = aa[2];
        float ang = sqrtf(x * x + y * y + z * z + 1e-8f);
        float inv = 1.f / ang;
        x *= inv; y *= inv; z *= inv;
        float cc = cosf(ang), ss = sinf(ang), C = 1.f - cc;
        float R[9];
        R[0] = cc + C * x * x;     R[1] = C * x * y - ss * z; R[2] = C * x * z + ss * y;
        R[3] = C * x * y + ss * z; R[4] = cc + C * y * y;     R[5] = C * y * z - ss * x;
        R[6] = C * x * z - ss * y; R[7] = C * y * z + ss * x; R[8] = cc + C * z * z;
#pragma unroll
        for (int e = 0; e < 9; e++) {
            sR[tid][e] = R[e];
            outRs[(size_t)b * (NJ * 9) + tid * 9 + e] = R[e];
        }
    }
    __syncthreads();

    for (int idx = tid; idx < NP; idx += 128) {
        int j = 1 + idx / 9, e = idx % 9;
        float d = (e == 0 || e == 4 || e == 8) ? 1.f : 0.f;
        g_pf[(size_t)b * NP + idx] = sR[j][e] - d;
    }

    if (tid < NJ) {
        const float* shp = inputs + (size_t)b * INW + 72;
#pragma unroll
        for (int c = 0; c < 3; c++) {
            float v = g_Jtmpl[tid * 3 + c];
#pragma unroll
            for (int n = 0; n < NBETA; n++)
                v += shp[n] * g_Jdirs[n * (NJ * 3) + tid * 3 + c];
            sJ[tid][c] = v;
        }
    }
    __syncthreads();

    if (tid < 12) {
        int r = tid / 4, col = tid % 4;
        sG[0][r * 4 + col] = (col < 3) ? sR[0][r * 3 + col] : sJ[0][r];
        for (int i = 1; i < NJ; i++) {
            __syncwarp(0xFFFu);
            int p = c_parents[i];
            float v;
            if (col < 3) {
                v = sG[p][r * 4 + 0] * sR[i][0 * 3 + col]
                  + sG[p][r * 4 + 1] * sR[i][1 * 3 + col]
                  + sG[p][r * 4 + 2] * sR[i][2 * 3 + col];
            } else {
                float t0 = sJ[i][0] - sJ[p][0];
                float t1 = sJ[i][1] - sJ[p][1];
                float t2 = sJ[i][2] - sJ[p][2];
                v = sG[p][r * 4 + 0] * t0 + sG[p][r * 4 + 1] * t1
                  + sG[p][r * 4 + 2] * t2 + sG[p][r * 4 + 3];
            }
            sG[i][r * 4 + col] = v;
        }
        __syncwarp(0xFFFu);
    }
    __syncthreads();

    // rel_A (duplicated: [b][j][12][2])
    for (int idx = tid; idx < NJ * 12; idx += 128) {
        int j = idx / 12, rc = idx % 12, r = rc / 4, col = rc % 4;
        float v;
        if (col < 3) v = sG[j][r * 4 + col];
        else v = sG[j][r * 4 + 3]
               - (sG[j][r * 4 + 0] * sJ[j][0] + sG[j][r * 4 + 1] * sJ[j][1]
                + sG[j][r * 4 + 2] * sJ[j][2]);
        size_t base = (size_t)b * (NJ * 24) + idx * 2;
        g_relA[base]     = v;
        g_relA[base + 1] = v;
    }
}

// =====================================================================
// K2: fused v_shaped + pose blend + LBS, packed f32x2 math
// 256 threads = 8 warps: warp -> (bgroup = wid&3 : 8 batches), (vsub = wid>>2)
// thread handles batches bgroup*8..+7 and vertex pair (pj, pj+64)
// =====================================================================
#define OFF_PF   0          // 207*64          = 13248  (pf duplicated, [kk][bt][2])
#define OFF_RA   13248      // 32*24*24        = 18432  (relA duplicated)
#define OFF_LBS  31680      // 24*128          = 3072
#define OFF_SD   34752      // 10*3*128        = 3840
#define OFF_TP   38592      // 3*128           = 384
#define OFF_SH   38976      // 10*32*2         = 640
#define OFF_PD   39616      // 2*23*384        = 17664  (double-buffered raw chunk)
#define SMEM_FLOATS 57280   // = 229120 bytes

__device__ __forceinline__ void stage_pd(const float* __restrict__ pdirs,
                                         int v0, int ch, unsigned dstb)
{
    int tid = threadIdx.x;
    if (tid < 192) {
        int gcol = v0 * 3 + tid * 2;
        int n = (gcol < NV3) ? 8 : 0;
        const float* src = pdirs + (size_t)(ch * KC) * NV3 + (n ? gcol : 0);
        unsigned dst = dstb + tid * 8;
#pragma unroll
        for (int kk = 0; kk < KC; kk++) {
            asm volatile("cp.async.ca.shared.global [%0], [%1], 8, %2;"
                         :: "r"(dst + kk * 1536), "l"(src + (size_t)kk * NV3), "r"(n)
                         : "memory");
        }
    }
}

__global__ void __launch_bounds__(256, 1)
k2_main(const float* __restrict__ inputs,
        const float* __restrict__ tmpl,
        const float* __restrict__ sdirs,
        const float* __restrict__ pdirs,
        float* __restrict__ outV)
{
    extern __shared__ float s[];
    float* s_pf  = s + OFF_PF;
    float* s_ra  = s + OFF_RA;
    float* s_lbs = s + OFF_LBS;
    float* s_sd  = s + OFF_SD;
    float* s_tp  = s + OFF_TP;
    float* s_sh  = s + OFF_SH;
    float* s_pd  = s + OFF_PD;

    int tid = threadIdx.x;
    int wid = tid >> 5, lane = tid & 31;
    int bgroup = wid & 3;
    int pj = ((wid >> 2) << 5) + lane;     // 0..63
    int b0 = blockIdx.y * BT;
    int v0 = blockIdx.x * VT;

    unsigned pd_s0 = su32(s_pd);

    // issue chunk 0 early
    stage_pd(pdirs, v0, 0, pd_s0);
    asm volatile("cp.async.commit_group;" ::: "memory");

    // pf: transpose + duplicate
    if (tid < NP) {
        const float* src = g_pf + (size_t)b0 * NP + tid;
        float* dst = s_pf + tid * 64;
#pragma unroll 4
        for (int bt = 0; bt < BT; bt++) {
            float v = src[(size_t)bt * NP];
            *(float2*)(dst + bt * 2) = make_float2(v, v);
        }
    }
    // relA: straight vector copy (already duplicated)
    {
        const float4* src = (const float4*)(g_relA + (size_t)b0 * (NJ * 24));
        float4* dst = (float4*)s_ra;
#pragma unroll
        for (int it = 0; it < 18; it++) dst[tid + it * 256] = src[tid + it * 256];
    }
    // lbs (coalesced via pre-transposed g_lbsT)
#pragma unroll
    for (int it = 0; it < 12; it++) {
        int idx = tid + it * 256;
        int j = idx >> 7, vl = idx & 127;
        int v = v0 + vl;
        s_lbs[idx] = (v < NV) ? g_lbsT[j * NV + v] : 0.f;
    }
    // template + shapedirs (de-interleave, div-by-3 hoisted)
    {
        int e0 = tid, q0 = e0 / 3, r0 = e0 - 3 * q0;
        int e1 = tid + 256, q1 = e1 / 3, r1 = e1 - 3 * q1;
        bool a1 = tid < 128;
        int gi0 = v0 * 3 + e0; bool in0 = gi0 < NV3;
        int gi1 = v0 * 3 + e1; bool in1 = gi1 < NV3;
        s_tp[r0 * VT + q0] = in0 ? tmpl[gi0] : 0.f;
        if (a1) s_tp[r1 * VT + q1] = in1 ? tmpl[gi1] : 0.f;
#pragma unroll
        for (int n = 0; n < NBETA; n++) {
            s_sd[(n * 3 + r0) * VT + q0] = in0 ? sdirs[(size_t)n * NV3 + gi0] : 0.f;
            if (a1) s_sd[(n * 3 + r1) * VT + q1] = in1 ? sdirs[(size_t)n * NV3 + gi1] : 0.f;
        }
    }
    // shape coeffs duplicated
    for (int idx = tid; idx < NBETA * BT; idx += 256) {
        int n = idx >> 5, bt = idx & 31;
        float v = inputs[(size_t)(b0 + bt) * INW + 72 + n];
        *(float2*)(s_sh + idx * 2) = make_float2(v, v);
    }
    __syncthreads();

    // ---- shape blend into packed accumulators ----
    u64 acc[8][3];
    {
        u64 t2[3];
#pragma unroll
        for (int c = 0; c < 3; c++)
            t2[c] = pack2(s_tp[c * VT + pj], s_tp[c * VT + pj + 64]);
#pragma unroll
        for (int i = 0; i < 8; i++)
#pragma unroll
            for (int c = 0; c < 3; c++) acc[i][c] = t2[c];
#pragma unroll
        for (int n = 0; n < NBETA; n++) {
            u64 sd2[3];
#pragma unroll
            for (int c = 0; c < 3; c++)
                sd2[c] = pack2(s_sd[(n * 3 + c) * VT + pj], s_sd[(n * 3 + c) * VT + pj + 64]);
            u64 sh8[8];
#pragma unroll
            for (int ih = 0; ih < 4; ih++) {
                U4 u; u.q = *(const uint4*)(s_sh + n * 64 + bgroup * 16 + ih * 4);
                sh8[2 * ih] = u.h[0]; sh8[2 * ih + 1] = u.h[1];
            }
#pragma unroll
            for (int i = 0; i < 8; i++)
#pragma unroll
                for (int c = 0; c < 3; c++)
                    acc[i][c] = ffma2(sh8[i], sd2[c], acc[i][c]);
        }
    }

    // ---- pose blend: 9 double-buffered chunks of 23 ----
    for (int ch = 0; ch < NCH; ch++) {
        if (ch + 1 < NCH) {
            stage_pd(pdirs, v0, ch + 1, pd_s0 + ((ch + 1) & 1) * (KC * 384 * 4));
            asm volatile("cp.async.commit_group;" ::: "memory");
            asm volatile("cp.async.wait_group 1;" ::: "memory");
        } else {
            asm volatile("cp.async.wait_group 0;" ::: "memory");
        }
        __syncthreads();
        const float* pd = s_pd + (ch & 1) * (KC * 384);
        int kb = ch * KC;
#pragma unroll
        for (int kk = 0; kk < KC; kk++) {
            u64 p2[3];
#pragma unroll
            for (int c = 0; c < 3; c++)
                p2[c] = pack2(pd[kk * 384 + pj * 3 + c], pd[kk * 384 + pj * 3 + c + 192]);
            u64 pf8[8];
            const float* pfp = s_pf + (kb + kk) * 64 + bgroup * 16;
#pragma unroll
            for (int ih = 0; ih < 4; ih++) {
                U4 u; u.q = *(const uint4*)(pfp + ih * 4);
                pf8[2 * ih] = u.h[0]; pf8[2 * ih + 1] = u.h[1];
            }
#pragma unroll
            for (int i = 0; i < 8; i++)
#pragma unroll
                for (int c = 0; c < 3; c++)
                    acc[i][c] = ffma2(pf8[i], p2[c], acc[i][c]);
        }
        __syncthreads();
    }

    // ---- LBS ----
    u64 o[8][3];
#pragma unroll
    for (int i = 0; i < 8; i++)
#pragma unroll
        for (int c = 0; c < 3; c++) o[i][c] = 0ull;

#pragma unroll 2
    for (int j = 0; j < NJ; j++) {
        u64 w2 = pack2(s_lbs[j * VT + pj], s_lbs[j * VT + pj + 64]);
#pragma unroll
        for (int i = 0; i < 8; i++) {
            const float* A = s_ra + ((size_t)(bgroup * 8 + i) * NJ + j) * 24;
            u64 a[12];
#pragma unroll
            for (int q = 0; q < 6; q++) {
                U4 u; u.q = *(const uint4*)(A + q * 4);
                a[2 * q] = u.h[0]; a[2 * q + 1] = u.h[1];
            }
            u64 x = acc[i][0], y = acc[i][1], z = acc[i][2], t;
            t = ffma2(a[0], x, a[3]);  t = ffma2(a[1], y, t);  t = ffma2(a[2],  z, t);
            o[i][0] = ffma2(w2, t, o[i][0]);
            t = ffma2(a[4], x, a[7]);  t = ffma2(a[5], y, t);  t = ffma2(a[6],  z, t);
            o[i][1] = ffma2(w2, t, o[i][1]);
            t = ffma2(a[8], x, a[11]); t = ffma2(a[9], y, t);  t = ffma2(a[10], z, t);
            o[i][2] = ffma2(w2, t, o[i][2]);
        }
    }

    // ---- store ----
    int v1 = v0 + pj;
    int v2v = v1 + 64;
#pragma unroll
    for (int i = 0; i < 8; i++) {
        size_t b = b0 + bgroup * 8 + i;
        float xa, xb, ya, yb, za, zb;
        unpk(o[i][0], xa, xb); unpk(o[i][1], ya, yb); unpk(o[i][2], za, zb);
        float* d1 = outV + (b * NV + v1) * 3;
        d1[0] = xa; d1[1] = ya; d1[2] = za;
        if (v2v < NV) {
            float* d2 = outV + (b * NV + v2v) * 3;
            d2[0] = xb; d2[1] = yb; d2[2] = zb;
        }
    }
}

// =====================================================================
// K3: joints = einsum('bvc,vk->bkc', vertices, joint_regressor)
// =====================================================================
__global__ void k3_joints(const float* __restrict__ verts,
                          float* __restrict__ outJ)
{
    int b = blockIdx.x, tid = threadIdx.x;
    float accj[NK * 3];
#pragma unroll
    for (int t = 0; t < NK * 3; t++) accj[t] = 0.f;

    for (int v = tid; v < NV; v += 256) {
        const float* p = &verts[((size_t)b * NV + v) * 3];
        float p0 = p[0], p1 = p[1], p2 = p[2];
#pragma unroll
        for (int k = 0; k < NK; k++) {
            float r = g_jregT[k * NV + v];
            accj[k * 3 + 0] += r * p0;
            accj[k * 3 + 1] += r * p1;
            accj[k * 3 + 2] += r * p2;
        }
    }
    __shared__ float sred[8][NK * 3];
    int lane = tid & 31, wid = tid >> 5;
#pragma unroll
    for (int t = 0; t < NK * 3; t++) {
        float val = accj[t];
#pragma unroll
        for (int off = 16; off > 0; off >>= 1)
            val += __shfl_down_sync(0xFFFFFFFFu, val, off);
        if (lane == 0) sred[wid][t] = val;
    }
    __syncthreads();
    if (tid < NK * 3) {
        float sv = 0.f;
#pragma unroll
        for (int w = 0; w < 8; w++) sv += sred[w][tid];
        outJ[(size_t)b * (NK * 3) + tid] = sv;
    }
}

// =====================================================================
extern "C" void kernel_launch(void* const* d_in, const int* in_sizes, int n_in,
                              void* d_out, int out_size)
{
    const float* inputs = (const float*)d_in[0];
    const float* vtempl = (const float*)d_in[1];
    const float* sdirs  = (const float*)d_in[2];
    const float* jreg24 = (const float*)d_in[3];
    const float* pdirs  = (const float*)d_in[4];
    const float* lbsw   = (const float*)d_in[5];
    const float* jreg19 = (const float*)d_in[6];

    float* out   = (float*)d_out;
    float* outV  = out;                                   // [B,V,3]
    float* outJ  = outV + (size_t)BN * NV * 3;            // [B,19,3]
    float* outRs = outJ + (size_t)BN * NK * 3;            // [B,24,3,3]

    size_t k2_smem = (size_t)SMEM_FLOATS * sizeof(float); // 229120 B
    cudaFuncSetAttribute(k2_main, cudaFuncAttributeMaxDynamicSharedMemorySize, (int)k2_smem);

    k0a_jointdirs<<<NJ * 3, 256>>>(vtempl, sdirs, jreg24);
    k0b_transpose<<<(NV * NK + 255) / 256, 256>>>(jreg19);
    k0c_lbsT<<<(NV * NJ + 255) / 256, 256>>>(lbsw);
    k1_batchprep<<<BN, 128>>>(inputs, outRs);
    dim3 g2((NV + VT - 1) / VT, BN / BT);
    k2_main<<<g2, 256, k2_smem>>>(inputs, vtempl, sdirs, pdirs, outV);
    k3_joints<<<BN, 256>>>(outV, outJ);
}

// round 8
// speedup vs baseline: 2.3458x; 1.0896x over previous
#include <cuda_runtime.h>
#include <math.h>
#include <stdint.h>

#define BN 1024
#define NV 6890
#define NV3 20670
#define NJ 24
#define NBETA 10
#define NP 207
#define NK 19
#define INW 82

#define BT 32      // batches per block (k2)
#define VT 192     // vertices per block (k2)
#define NPAIR 96   // vertex pairs per block
#define KC 9       // K-chunk of pose blend (23*9 = 207)
#define NCH 23

typedef unsigned long long u64;

// ---- scratch (device globals) ----
__device__ float g_Jdirs[NBETA * NJ * 3];
__device__ float g_Jtmpl[NJ * 3];
__device__ float g_jregT[NK * NV];            // [19][V]
__device__ float g_lbsT[NJ * NV];             // [24][V]
__device__ float g_pdT[NP * 3 * NV];          // [207*3][V] channel planes (17.1 MB)
__device__ float g_sdT[NBETA * 3 * NV];       // [30][V]
__device__ float g_tpT[3 * NV];               // [3][V]
__device__ float g_pf[BN * NP];               // pose features
__device__ __align__(16) float g_relA[BN * NJ * 12 * 2];   // duplicated pairs

__constant__ int c_parents[NJ] = {0,0,0,0,1,2,3,4,5,6,7,8,9,9,9,12,13,14,16,17,18,19,20,21};

// ---- packed f32x2 helpers ----
__device__ __forceinline__ u64 ffma2(u64 a, u64 b, u64 c) {
    u64 d;
    asm("fma.rn.f32x2 %0, %1, %2, %3;" : "=l"(d) : "l"(a), "l"(b), "l"(c));
    return d;
}
__device__ __forceinline__ u64 pack2(float a, float b) {
    u64 r;
    asm("mov.b64 %0, {%1, %2};" : "=l"(r) : "f"(a), "f"(b));
    return r;
}
__device__ __forceinline__ void unpk(u64 v, float& a, float& b) {
    asm("mov.b64 {%0, %1}, %2;" : "=f"(a), "=f"(b) : "l"(v));
}
union U4 { uint4 q; u64 h[2]; };

__device__ __forceinline__ unsigned su32(const void* p) {
    return (unsigned)__cvta_generic_to_shared(p);
}

// =====================================================================
// K0a: fold smpl_j_regressor into shapedirs/template
// =====================================================================
__global__ void k0a_jointdirs(const float* __restrict__ tmpl,
                              const float* __restrict__ sdirs,
                              const float* __restrict__ jreg)
{
    int k = blockIdx.x / 3, c = blockIdx.x % 3;
    float acc[NBETA + 1];
#pragma unroll
    for (int t = 0; t <= NBETA; t++) acc[t] = 0.f;

    for (int v = threadIdx.x; v < NV; v += 256) {
        float r = jreg[v * NJ + k];
        acc[0] += tmpl[v * 3 + c] * r;
#pragma unroll
        for (int n = 0; n < NBETA; n++)
            acc[1 + n] += sdirs[n * NV3 + v * 3 + c] * r;
    }
    __shared__ float red[256];
    for (int t = 0; t <= NBETA; t++) {
        __syncthreads();
        red[threadIdx.x] = acc[t];
        __syncthreads();
        for (int s = 128; s > 0; s >>= 1) {
            if (threadIdx.x < s) red[threadIdx.x] += red[threadIdx.x + s];
            __syncthreads();
        }
        if (threadIdx.x == 0) {
            if (t == 0) g_Jtmpl[k * 3 + c] = red[0];
            else        g_Jdirs[(t - 1) * (NJ * 3) + k * 3 + c] = red[0];
        }
    }
}

// =====================================================================
// K0t1: row transposes into channel-plane layouts
// grid = 621 (pdT) + 30 (sdT) + 3 (tpT) = 654 blocks x 256
// =====================================================================
__global__ void k0t1_planes(const float* __restrict__ pdirs,
                            const float* __restrict__ sdirs,
                            const float* __restrict__ tmpl)
{
    int r = blockIdx.x;
    if (r < NP * 3) {
        int k = r / 3, c = r - 3 * k;
        const float* src = pdirs + (size_t)k * NV3 + c;
        float* dst = g_pdT + (size_t)r * NV;
        for (int v = threadIdx.x; v < NV; v += 256)
            dst[v] = src[3 * v];
    } else if (r < NP * 3 + NBETA * 3) {
        int rr = r - NP * 3;
        int n = rr / 3, c = rr - 3 * n;
        const float* src = sdirs + (size_t)n * NV3 + c;
        float* dst = g_sdT + (size_t)rr * NV;
        for (int v = threadIdx.x; v < NV; v += 256)
            dst[v] = src[3 * v];
    } else {
        int c = r - (NP * 3 + NBETA * 3);
        float* dst = g_tpT + (size_t)c * NV;
        for (int v = threadIdx.x; v < NV; v += 256)
            dst[v] = tmpl[3 * v + c];
    }
}

// K0t2: elementwise transposes for jreg19 and lbs weights
__global__ void k0t2_regs(const float* __restrict__ jr,
                          const float* __restrict__ lbs)
{
    int idx = blockIdx.x * blockDim.x + threadIdx.x;
    if (idx < NV * NK) {
        int v = idx / NK, k = idx - v * NK;
        g_jregT[k * NV + v] = jr[idx];
    } else if (idx < NV * NK + NV * NJ) {
        int i2 = idx - NV * NK;
        int v = i2 / NJ, j = i2 - v * NJ;
        g_lbsT[j * NV + v] = lbs[i2];
    }
}

// =====================================================================
// K1: per-batch rotations, pose features, joints, kinematic chain, rel_A
// =====================================================================
__global__ void k1_batchprep(const float* __restrict__ inputs,
                             float* __restrict__ outRs)
{
    int b = blockIdx.x;
    int tid = threadIdx.x;
    __shared__ float sR[NJ][9];
    __shared__ float sJ[NJ][3];
    __shared__ float sG[NJ][12];

    if (tid < NJ) {
        const float* aa = inputs + (size_t)b * INW + tid * 3;
        float x = aa[0], y = aa[1], z = aa[2];
        float ang = sqrtf(x * x + y * y + z * z + 1e-8f);
        float inv = 1.f / ang;
        x *= inv; y *= inv; z *= inv;
        float cc = cosf(ang), ss = sinf(ang), C = 1.f - cc;
        float R[9];
        R[0] = cc + C * x * x;     R[1] = C * x * y - ss * z; R[2] = C * x * z + ss * y;
        R[3] = C * x * y + ss * z; R[4] = cc + C * y * y;     R[5] = C * y * z - ss * x;
        R[6] = C * x * z - ss * y; R[7] = C * y * z + ss * x; R[8] = cc + C * z * z;
#pragma unroll
        for (int e = 0; e < 9; e++) {
            sR[tid][e] = R[e];
            outRs[(size_t)b * (NJ * 9) + tid * 9 + e] = R[e];
        }
    }
    __syncthreads();

    for (int idx = tid; idx < NP; idx += 128) {
        int j = 1 + idx / 9, e = idx % 9;
        float d = (e == 0 || e == 4 || e == 8) ? 1.f : 0.f;
        g_pf[(size_t)b * NP + idx] = sR[j][e] - d;
    }

    if (tid < NJ) {
        const float* shp = inputs + (size_t)b * INW + 72;
#pragma unroll
        for (int c = 0; c < 3; c++) {
            float v = g_Jtmpl[tid * 3 + c];
#pragma unroll
            for (int n = 0; n < NBETA; n++)
                v += shp[n] * g_Jdirs[n * (NJ * 3) + tid * 3 + c];
            sJ[tid][c] = v;
        }
    }
    __syncthreads();

    if (tid < 12) {
        int r = tid / 4, col = tid % 4;
        sG[0][r * 4 + col] = (col < 3) ? sR[0][r * 3 + col] : sJ[0][r];
        for (int i = 1; i < NJ; i++) {
            __syncwarp(0xFFFu);
            int p = c_parents[i];
            float v;
            if (col < 3) {
                v = sG[p][r * 4 + 0] * sR[i][0 * 3 + col]
                  + sG[p][r * 4 + 1] * sR[i][1 * 3 + col]
                  + sG[p][r * 4 + 2] * sR[i][2 * 3 + col];
            } else {
                float t0 = sJ[i][0] - sJ[p][0];
                float t1 = sJ[i][1] - sJ[p][1];
                float t2 = sJ[i][2] - sJ[p][2];
                v = sG[p][r * 4 + 0] * t0 + sG[p][r * 4 + 1] * t1
                  + sG[p][r * 4 + 2] * t2 + sG[p][r * 4 + 3];
            }
            sG[i][r * 4 + col] = v;
        }
        __syncwarp(0xFFFu);
    }
    __syncthreads();

    // rel_A (duplicated: [b][j][12][2])
    for (int idx = tid; idx < NJ * 12; idx += 128) {
        int j = idx / 12, rc = idx % 12, r = rc / 4, col = rc % 4;
        float v;
        if (col < 3) v = sG[j][r * 4 + col];
        else v = sG[j][r * 4 + 3]
               - (sG[j][r * 4 + 0] * sJ[j][0] + sG[j][r * 4 + 1] * sJ[j][1]
                + sG[j][r * 4 + 2] * sJ[j][2]);
        size_t base = (size_t)b * (NJ * 24) + idx * 2;
        g_relA[base]     = v;
        g_relA[base + 1] = v;
    }
}

// =====================================================================
// K2: fused v_shaped + pose blend + LBS, packed f32x2 math
// 384 threads = 12 warps: bgroup = wid&3 (8 batches), vsub = wid>>2 (0..2)
// thread handles vertex pair (v0+2p, v0+2p+1), p = vsub*32+lane
// =====================================================================
#define OFF_PF   0          // 207*64   = 13248 (pf duplicated [kk][bt][2])
#define OFF_RA   13248      // 32*24*24 = 18432 (relA duplicated)
#define OFF_LBS  31680      // 24*192   = 4608
#define OFF_SD   36288      // 30*192   = 5760 (channel planes)
#define OFF_TP   42048      // 3*192    = 576
#define OFF_SH   42624      // 10*32*2  = 640
#define OFF_PD   43264      // 2*9*3*192 = 10368 (double-buffered, c-planes)
#define SMEM_FLOATS 53632   // = 214528 bytes

#define PD_CHUNK (KC * 3 * VT)   // 5184 floats per buffer

__device__ __forceinline__ void stage_pd(int v0, int ch, unsigned dstb)
{
    // chunk ch covers g_pdT rows [ch*27, ch*27+27), columns v0..v0+191 (8B units)
    int tid = threadIdx.x;
#pragma unroll
    for (int it = 0; it < 7; it++) {
        int idx = tid + it * 384;
        if (idx < 27 * 96) {
            int rr = idx / 96, off = idx - rr * 96;
            int col = v0 + off * 2;
            int n = (col < NV) ? 8 : 0;
            const float* src = g_pdT + (size_t)(ch * 27 + rr) * NV + (n ? col : 0);
            unsigned dst = dstb + (rr * VT + off * 2) * 4;
            asm volatile("cp.async.ca.shared.global [%0], [%1], 8, %2;"
                         :: "r"(dst), "l"(src), "r"(n) : "memory");
        }
    }
}

__global__ void __launch_bounds__(384, 1)
k2_main(const float* __restrict__ inputs,
        float* __restrict__ outV)
{
    extern __shared__ float s[];
    float* s_pf  = s + OFF_PF;
    float* s_ra  = s + OFF_RA;
    float* s_lbs = s + OFF_LBS;
    float* s_sd  = s + OFF_SD;
    float* s_tp  = s + OFF_TP;
    float* s_sh  = s + OFF_SH;
    float* s_pd  = s + OFF_PD;

    int tid = threadIdx.x;
    int wid = tid >> 5, lane = tid & 31;
    int bgroup = wid & 3;
    int p = ((wid >> 2) << 5) + lane;      // 0..95 (pair index)
    int b0 = blockIdx.y * BT;
    int v0 = blockIdx.x * VT;

    unsigned pd_s0 = su32(s_pd);

    // issue chunk 0 early
    stage_pd(v0, 0, pd_s0);
    asm volatile("cp.async.commit_group;" ::: "memory");

    // pf: transpose + duplicate
    if (tid < NP) {
        const float* src = g_pf + (size_t)b0 * NP + tid;
        float* dst = s_pf + tid * 64;
#pragma unroll 4
        for (int bt = 0; bt < BT; bt++) {
            float v = src[(size_t)bt * NP];
            *(float2*)(dst + bt * 2) = make_float2(v, v);
        }
    }
    // relA: straight vector copy (already duplicated)
    {
        const float4* src = (const float4*)(g_relA + (size_t)b0 * (NJ * 24));
        float4* dst = (float4*)s_ra;
#pragma unroll
        for (int it = 0; it < 12; it++) dst[tid + it * 384] = src[tid + it * 384];
    }
    // lbs (coalesced from g_lbsT)
#pragma unroll
    for (int it = 0; it < 12; it++) {
        int idx = tid + it * 384;
        int j = idx / VT, vl = idx - j * VT;
        int v = v0 + vl;
        s_lbs[idx] = (v < NV) ? g_lbsT[j * NV + v] : 0.f;
    }
    // shapedirs channel planes (30 rows)
#pragma unroll
    for (int it = 0; it < 15; it++) {
        int idx = tid + it * 384;
        int rr = idx / VT, vl = idx - rr * VT;
        int v = v0 + vl;
        s_sd[idx] = (v < NV) ? g_sdT[(size_t)rr * NV + v] : 0.f;
    }
    // template planes (3 rows = 576 entries; strided loop, full coverage)
    for (int idx = tid; idx < 3 * VT; idx += 384) {
        int rr = idx / VT, vl = idx - rr * VT;
        int v = v0 + vl;
        s_tp[idx] = (v < NV) ? g_tpT[(size_t)rr * NV + v] : 0.f;
    }
    // shape coeffs duplicated
    if (tid < NBETA * BT) {
        int n = tid >> 5, bt = tid & 31;
        float v = inputs[(size_t)(b0 + bt) * INW + 72 + n];
        *(float2*)(s_sh + tid * 2) = make_float2(v, v);
    }
    __syncthreads();

    // ---- shape blend into packed accumulators ----
    u64 acc[8][3];
    {
        u64 t2[3];
#pragma unroll
        for (int c = 0; c < 3; c++)
            t2[c] = *(const u64*)(s_tp + c * VT + 2 * p);
#pragma unroll
        for (int i = 0; i < 8; i++)
#pragma unroll
            for (int c = 0; c < 3; c++) acc[i][c] = t2[c];
#pragma unroll
        for (int n = 0; n < NBETA; n++) {
            u64 sd2[3];
#pragma unroll
            for (int c = 0; c < 3; c++)
                sd2[c] = *(const u64*)(s_sd + (n * 3 + c) * VT + 2 * p);
            u64 sh8[8];
#pragma unroll
            for (int ih = 0; ih < 4; ih++) {
                U4 u; u.q = *(const uint4*)(s_sh + n * 64 + bgroup * 16 + ih * 4);
                sh8[2 * ih] = u.h[0]; sh8[2 * ih + 1] = u.h[1];
            }
#pragma unroll
            for (int i = 0; i < 8; i++)
#pragma unroll
                for (int c = 0; c < 3; c++)
                    acc[i][c] = ffma2(sh8[i], sd2[c], acc[i][c]);
        }
    }

    // ---- pose blend: 23 double-buffered chunks of 9 ----
    for (int ch = 0; ch < NCH; ch++) {
        if (ch + 1 < NCH) {
            stage_pd(v0, ch + 1, pd_s0 + ((ch + 1) & 1) * (PD_CHUNK * 4));
            asm volatile("cp.async.commit_group;" ::: "memory");
            asm volatile("cp.async.wait_group 1;" ::: "memory");
        } else {
            asm volatile("cp.async.wait_group 0;" ::: "memory");
        }
        __syncthreads();
        const float* pd = s_pd + (ch & 1) * PD_CHUNK;
        int kb = ch * KC;
#pragma unroll
        for (int kk = 0; kk < KC; kk++) {
            u64 p2[3];
#pragma unroll
            for (int c = 0; c < 3; c++)
                p2[c] = *(const u64*)(pd + (kk * 3 + c) * VT + 2 * p);
            u64 pf8[8];
            const float* pfp = s_pf + (kb + kk) * 64 + bgroup * 16;
#pragma unroll
            for (int ih = 0; ih < 4; ih++) {
                U4 u; u.q = *(const uint4*)(pfp + ih * 4);
                pf8[2 * ih] = u.h[0]; pf8[2 * ih + 1] = u.h[1];
            }
#pragma unroll
            for (int i = 0; i < 8; i++)
#pragma unroll
                for (int c = 0; c < 3; c++)
                    acc[i][c] = ffma2(pf8[i], p2[c], acc[i][c]);
        }
        __syncthreads();
    }

    // ---- LBS ----
    u64 o[8][3];
#pragma unroll
    for (int i = 0; i < 8; i++)
#pragma unroll
        for (int c = 0; c < 3; c++) o[i][c] = 0ull;

    for (int j = 0; j < NJ; j++) {
        u64 w2 = *(const u64*)(s_lbs + j * VT + 2 * p);
#pragma unroll
        for (int i = 0; i < 8; i++) {
            const float* A = s_ra + ((size_t)(bgroup * 8 + i) * NJ + j) * 24;
            u64 x = acc[i][0], y = acc[i][1], z = acc[i][2], t;
            {
                U4 u0; u0.q = *(const uint4*)(A);
                U4 u1; u1.q = *(const uint4*)(A + 4);
                t = ffma2(u0.h[0], x, u1.h[1]);
                t = ffma2(u0.h[1], y, t);
                t = ffma2(u1.h[0], z, t);
                o[i][0] = ffma2(w2, t, o[i][0]);
            }
            {
                U4 u0; u0.q = *(const uint4*)(A + 8);
                U4 u1; u1.q = *(const uint4*)(A + 12);
                t = ffma2(u0.h[0], x, u1.h[1]);
                t = ffma2(u0.h[1], y, t);
                t = ffma2(u1.h[0], z, t);
                o[i][1] = ffma2(w2, t, o[i][1]);
            }
            {
                U4 u0; u0.q = *(const uint4*)(A + 16);
                U4 u1; u1.q = *(const uint4*)(A + 20);
                t = ffma2(u0.h[0], x, u1.h[1]);
                t = ffma2(u0.h[1], y, t);
                t = ffma2(u1.h[0], z, t);
                o[i][2] = ffma2(w2, t, o[i][2]);
            }
        }
    }

    // ---- store: 6 contiguous floats per thread (two adjacent vertices) ----
    int v1 = v0 + 2 * p;
    if (v1 < NV) {   // NV even, v1 even -> both vertices valid
#pragma unroll
        for (int i = 0; i < 8; i++) {
            size_t b = b0 + bgroup * 8 + i;
            float xa, xb, ya, yb, za, zb;
            unpk(o[i][0], xa, xb); unpk(o[i][1], ya, yb); unpk(o[i][2], za, zb);
            float* d = outV + (b * NV + v1) * 3;
            *(float2*)(d)     = make_float2(xa, ya);
            *(float2*)(d + 2) = make_float2(za, xb);
            *(float2*)(d + 4) = make_float2(yb, zb);
        }
    }
}

// =====================================================================
// K3: joints — 2 batches per block, batch dim packed into f32x2
// =====================================================================
__global__ void __launch_bounds__(256)
k3_joints(const float* __restrict__ verts, float* __restrict__ outJ)
{
    int b0 = blockIdx.x * 2, tid = threadIdx.x;
    u64 acc[NK * 3];
#pragma unroll
    for (int t = 0; t < NK * 3; t++) acc[t] = 0ull;

    for (int v = tid; v < NV; v += 256) {
        const float* pA = verts + ((size_t)b0 * NV + v) * 3;
        const float* pB = pA + (size_t)NV * 3;
        u64 px = pack2(pA[0], pB[0]);
        u64 py = pack2(pA[1], pB[1]);
        u64 pz = pack2(pA[2], pB[2]);
#pragma unroll
        for (int k = 0; k < NK; k++) {
            float r = g_jregT[k * NV + v];
            u64 r2 = pack2(r, r);
            acc[k * 3 + 0] = ffma2(r2, px, acc[k * 3 + 0]);
            acc[k * 3 + 1] = ffma2(r2, py, acc[k * 3 + 1]);
            acc[k * 3 + 2] = ffma2(r2, pz, acc[k * 3 + 2]);
        }
    }
    __shared__ u64 sred[8][NK * 3];
    int lane = tid & 31, wid = tid >> 5;
#pragma unroll
    for (int t = 0; t < NK * 3; t++) {
        float lo, hi;
        unpk(acc[t], lo, hi);
#pragma unroll
        for (int off = 16; off > 0; off >>= 1) {
            lo += __shfl_down_sync(0xFFFFFFFFu, lo, off);
            hi += __shfl_down_sync(0xFFFFFFFFu, hi, off);
        }
        if (lane == 0) sred[wid][t] = pack2(lo, hi);
    }
    __syncthreads();
    if (tid < NK * 3) {
        float slo = 0.f, shi = 0.f;
#pragma unroll
        for (int w = 0; w < 8; w++) {
            float lo, hi; unpk(sred[w][tid], lo, hi);
            slo += lo; shi += hi;
        }
        outJ[(size_t)b0 * (NK * 3) + tid] = slo;
        outJ[(size_t)(b0 + 1) * (NK * 3) + tid] = shi;
    }
}

// =====================================================================
extern "C" void kernel_launch(void* const* d_in, const int* in_sizes, int n_in,
                              void* d_out, int out_size)
{
    const float* inputs = (const float*)d_in[0];
    const float* vtempl = (const float*)d_in[1];
    const float* sdirs  = (const float*)d_in[2];
    const float* jreg24 = (const float*)d_in[3];
    const float* pdirs  = (const float*)d_in[4];
    const float* lbsw   = (const float*)d_in[5];
    const float* jreg19 = (const float*)d_in[6];

    float* out   = (float*)d_out;
    float* outV  = out;                                   // [B,V,3]
    float* outJ  = outV + (size_t)BN * NV * 3;            // [B,19,3]
    float* outRs = outJ + (size_t)BN * NK * 3;            // [B,24,3,3]

    size_t k2_smem = (size_t)SMEM_FLOATS * sizeof(float); // 214528 B
    cudaFuncSetAttribute(k2_main, cudaFuncAttributeMaxDynamicSharedMemorySize, (int)k2_smem);

    k0a_jointdirs<<<NJ * 3, 256>>>(vtempl, sdirs, jreg24);
    k0t1_planes<<<NP * 3 + NBETA * 3 + 3, 256>>>(pdirs, sdirs, vtempl);
    k0t2_regs<<<(NV * NK + NV * NJ + 255) / 256, 256>>>(jreg19, lbsw);
    k1_batchprep<<<BN, 128>>>(inputs, outRs);
    dim3 g2((NV + VT - 1) / VT, BN / BT);
    k2_main<<<g2, 384, k2_smem>>>(inputs, outV);
    k3_joints<<<BN / 2, 256>>>(outV, outJ);
}

// round 12
// speedup vs baseline: 2.8436x; 1.2122x over previous
#include <cuda_runtime.h>
#include <math.h>
#include <stdint.h>

#define BN 1024
#define NV 6890
#define NVP 6912          // padded vertex count (64-aligned)
#define NV3 20670
#define NJ 24
#define NBETA 10
#define NP 207
#define NK 19
#define INW 82

#define KTOT 224          // padded K for pose GEMM (207 + 17 zeros)
#define BT 32             // batches per block
#define VT2 64            // vertices per block
#define ASTR 228          // s_A row stride (floats)
#define WSTR 200          // s_W row stride
#define VPSTR 200         // s_vp row stride

typedef unsigned long long u64;

// ---- device scratch ----
__device__ float g_Jdirs[NBETA * NJ * 3];
__device__ float g_Jtmpl[NJ * 3];
__device__ float g_jregT[NK * NV];
__device__ float g_lbsT[NJ * NV];
__device__ float g_sdT[NBETA * 3 * NV];
__device__ float g_tpT[3 * NV];
__device__ __align__(16) float g_W[KTOT * 3 * NVP];     // tf32 pose dirs planes [k][c][v]
__device__ __align__(16) float g_F[BN * KTOT];          // tf32 pose features
__device__ __align__(16) float g_relA[BN * NJ * 12 * 2];

__constant__ int c_parents[NJ] = {0,0,0,0,1,2,3,4,5,6,7,8,9,9,9,12,13,14,16,17,18,19,20,21};

// ---- helpers ----
__device__ __forceinline__ u64 ffma2(u64 a, u64 b, u64 c) {
    u64 d; asm("fma.rn.f32x2 %0, %1, %2, %3;" : "=l"(d) : "l"(a), "l"(b), "l"(c)); return d;
}
__device__ __forceinline__ u64 add2(u64 a, u64 b) {
    u64 d; asm("add.rn.f32x2 %0, %1, %2;" : "=l"(d) : "l"(a), "l"(b)); return d;
}
__device__ __forceinline__ u64 pack2(float a, float b) {
    u64 r; asm("mov.b64 %0, {%1, %2};" : "=l"(r) : "f"(a), "f"(b)); return r;
}
__device__ __forceinline__ void unpk(u64 v, float& a, float& b) {
    asm("mov.b64 {%0, %1}, %2;" : "=f"(a), "=f"(b) : "l"(v));
}
__device__ __forceinline__ float to_tf32(float x) {
    uint32_t u; asm("cvt.rna.tf32.f32 %0, %1;" : "=r"(u) : "f"(x));
    return __uint_as_float(u);
}
__device__ __forceinline__ void mma_tf32(float* d, uint32_t a0, uint32_t a1,
                                         uint32_t a2, uint32_t a3,
                                         uint32_t b0, uint32_t b1) {
    asm volatile("mma.sync.aligned.m16n8k8.row.col.f32.tf32.tf32.f32 "
                 "{%0,%1,%2,%3}, {%4,%5,%6,%7}, {%8,%9}, {%0,%1,%2,%3};"
                 : "+f"(d[0]), "+f"(d[1]), "+f"(d[2]), "+f"(d[3])
                 : "r"(a0), "r"(a1), "r"(a2), "r"(a3), "r"(b0), "r"(b1));
}
union U4 { uint4 q; u64 h[2]; };
__device__ __forceinline__ unsigned su32(const void* p) {
    return (unsigned)__cvta_generic_to_shared(p);
}

// =====================================================================
// K0a: fold smpl_j_regressor into shapedirs/template
// =====================================================================
__global__ void k0a_jointdirs(const float* __restrict__ tmpl,
                              const float* __restrict__ sdirs,
                              const float* __restrict__ jreg)
{
    int k = blockIdx.x / 3, c = blockIdx.x % 3;
    float acc[NBETA + 1];
#pragma unroll
    for (int t = 0; t <= NBETA; t++) acc[t] = 0.f;
    for (int v = threadIdx.x; v < NV; v += 256) {
        float r = jreg[v * NJ + k];
        acc[0] += tmpl[v * 3 + c] * r;
#pragma unroll
        for (int n = 0; n < NBETA; n++)
            acc[1 + n] += sdirs[n * NV3 + v * 3 + c] * r;
    }
    __shared__ float red[256];
    for (int t = 0; t <= NBETA; t++) {
        __syncthreads();
        red[threadIdx.x] = acc[t];
        __syncthreads();
        for (int s = 128; s > 0; s >>= 1) {
            if (threadIdx.x < s) red[threadIdx.x] += red[threadIdx.x + s];
            __syncthreads();
        }
        if (threadIdx.x == 0) {
            if (t == 0) g_Jtmpl[k * 3 + c] = red[0];
            else        g_Jdirs[(t - 1) * (NJ * 3) + k * 3 + c] = red[0];
        }
    }
}

// =====================================================================
// K0w: build tf32 weight planes g_W[k][c][NVP] (zeros for k>=207, v>=NV)
// =====================================================================
__global__ void k0w_build(const float* __restrict__ pdirs)
{
    int r = blockIdx.x;
    int k = r / 3, c = r - 3 * k;
    float* dst = g_W + (size_t)r * NVP;
    if (k < NP) {
        const float* src = pdirs + (size_t)k * NV3 + c;
        for (int v = threadIdx.x; v < NVP; v += 256)
            dst[v] = (v < NV) ? to_tf32(src[3 * v]) : 0.f;
    } else {
        for (int v = threadIdx.x; v < NVP; v += 256) dst[v] = 0.f;
    }
}

// K0t1b: sdT / tpT channel planes (fp32)
__global__ void k0t1b_planes(const float* __restrict__ sdirs,
                             const float* __restrict__ tmpl)
{
    int r = blockIdx.x;
    if (r < NBETA * 3) {
        int n = r / 3, c = r - 3 * n;
        const float* src = sdirs + (size_t)n * NV3 + c;
        float* dst = g_sdT + (size_t)r * NV;
        for (int v = threadIdx.x; v < NV; v += 256) dst[v] = src[3 * v];
    } else {
        int c = r - NBETA * 3;
        float* dst = g_tpT + (size_t)c * NV;
        for (int v = threadIdx.x; v < NV; v += 256) dst[v] = tmpl[3 * v + c];
    }
}

// K0t2: transposes for jreg19 and lbs weights
__global__ void k0t2_regs(const float* __restrict__ jr,
                          const float* __restrict__ lbs)
{
    int idx = blockIdx.x * blockDim.x + threadIdx.x;
    if (idx < NV * NK) {
        int v = idx / NK, k = idx - v * NK;
        g_jregT[k * NV + v] = jr[idx];
    } else if (idx < NV * NK + NV * NJ) {
        int i2 = idx - NV * NK;
        int v = i2 / NJ, j = i2 - v * NJ;
        g_lbsT[j * NV + v] = lbs[i2];
    }
}

// =====================================================================
// K1: per-batch rotations, tf32 pose features, chain, rel_A (duplicated)
// =====================================================================
__global__ void k1_batchprep(const float* __restrict__ inputs,
                             float* __restrict__ outRs)
{
    int b = blockIdx.x;
    int tid = threadIdx.x;
    __shared__ float sR[NJ][9];
    __shared__ float sJ[NJ][3];
    __shared__ float sG[NJ][12];

    if (tid < NJ) {
        const float* aa = inputs + (size_t)b * INW + tid * 3;
        float x = aa[0], y = aa[1], z = aa[2];
        float ang = sqrtf(x * x + y * y + z * z + 1e-8f);
        float inv = 1.f / ang;
        x *= inv; y *= inv; z *= inv;
        float cc = cosf(ang), ss = sinf(ang), C = 1.f - cc;
        float R[9];
        R[0] = cc + C * x * x;     R[1] = C * x * y - ss * z; R[2] = C * x * z + ss * y;
        R[3] = C * x * y + ss * z; R[4] = cc + C * y * y;     R[5] = C * y * z - ss * x;
        R[6] = C * x * z - ss * y; R[7] = C * y * z + ss * x; R[8] = cc + C * z * z;
#pragma unroll
        for (int e = 0; e < 9; e++) {
            sR[tid][e] = R[e];
            outRs[(size_t)b * (NJ * 9) + tid * 9 + e] = R[e];
        }
    }
    __syncthreads();

    // tf32 pose features (224 padded)
    for (int idx = tid; idx < KTOT; idx += 128) {
        float val = 0.f;
        if (idx < NP) {
            int j = 1 + idx / 9, e = idx % 9;
            float d = (e == 0 || e == 4 || e == 8) ? 1.f : 0.f;
            val = to_tf32(sR[j][e] - d);
        }
        g_F[(size_t)b * KTOT + idx] = val;
    }

    if (tid < NJ) {
        const float* shp = inputs + (size_t)b * INW + 72;
#pragma unroll
        for (int c = 0; c < 3; c++) {
            float v = g_Jtmpl[tid * 3 + c];
#pragma unroll
            for (int n = 0; n < NBETA; n++)
                v += shp[n] * g_Jdirs[n * (NJ * 3) + tid * 3 + c];
            sJ[tid][c] = v;
        }
    }
    __syncthreads();

    if (tid < 12) {
        int r = tid / 4, col = tid % 4;
        sG[0][r * 4 + col] = (col < 3) ? sR[0][r * 3 + col] : sJ[0][r];
        for (int i = 1; i < NJ; i++) {
            __syncwarp(0xFFFu);
            int p = c_parents[i];
            float v;
            if (col < 3) {
                v = sG[p][r * 4 + 0] * sR[i][0 * 3 + col]
                  + sG[p][r * 4 + 1] * sR[i][1 * 3 + col]
                  + sG[p][r * 4 + 2] * sR[i][2 * 3 + col];
            } else {
                float t0 = sJ[i][0] - sJ[p][0];
                float t1 = sJ[i][1] - sJ[p][1];
                float t2 = sJ[i][2] - sJ[p][2];
                v = sG[p][r * 4 + 0] * t0 + sG[p][r * 4 + 1] * t1
                  + sG[p][r * 4 + 2] * t2 + sG[p][r * 4 + 3];
            }
            sG[i][r * 4 + col] = v;
        }
        __syncwarp(0xFFFu);
    }
    __syncthreads();

    for (int idx = tid; idx < NJ * 12; idx += 128) {
        int j = idx / 12, rc = idx % 12, r = rc / 4, col = rc % 4;
        float v;
        if (col < 3) v = sG[j][r * 4 + col];
        else v = sG[j][r * 4 + 3]
               - (sG[j][r * 4 + 0] * sJ[j][0] + sG[j][r * 4 + 1] * sJ[j][1]
                + sG[j][r * 4 + 2] * sJ[j][2]);
        size_t base = (size_t)b * (NJ * 24) + idx * 2;
        g_relA[base]     = v;
        g_relA[base + 1] = v;
    }
}

// =====================================================================
// K2: tf32 mma pose GEMM + scalar shape/template + FFMA2 LBS
// 256 threads = 8 warps. GEMM: warp w -> mh=w&1 (16 batches), nb=w>>1 (48 cols)
// LBS: warp w -> batches 4w..4w+3, lane = vertex pair
// =====================================================================
#define OFF_A    0                      // 32*228 = 7296
#define OFF_W    7296                   // 2*32*200 = 12800
#define OFF_VP   20096                  // 32*200 = 6400
#define OFF_RA   26496                  // 32*24*24 = 18432
#define OFF_LBS  44928                  // 24*64 = 1536
#define OFF_SD   46464                  // 30*64 = 1920
#define OFF_TP   48384                  // 3*64 = 192
#define OFF_SHD  48576                  // 10*32*2 = 640
#define SMEM_FLOATS 49216               // 196864 bytes

__device__ __forceinline__ void stage_w(int v0, int ck, unsigned dstb)
{
    int tid = threadIdx.x;
#pragma unroll
    for (int it = 0; it < 6; it++) {
        int idx = tid + it * 256;             // 0..1535
        int kk = idx / 48, rem = idx - kk * 48;
        int c = rem >> 4, q = rem & 15;
        const float* src = g_W + ((size_t)(ck * 32 + kk) * 3 + c) * NVP + v0 + q * 4;
        unsigned dst = dstb + (kk * WSTR + c * 64 + q * 4) * 4;
        asm volatile("cp.async.ca.shared.global [%0], [%1], 16;"
                     :: "r"(dst), "l"(src) : "memory");
    }
}

__global__ void __launch_bounds__(256, 1)
k2_main(const float* __restrict__ inputs,
        float* __restrict__ outV)
{
    extern __shared__ float s[];
    float* s_A   = s + OFF_A;
    float* s_W   = s + OFF_W;
    float* s_vp  = s + OFF_VP;
    float* s_ra  = s + OFF_RA;
    float* s_lbs = s + OFF_LBS;
    float* s_sd  = s + OFF_SD;
    float* s_tp  = s + OFF_TP;
    float* s_shd = s + OFF_SHD;

    int tid = threadIdx.x;
    int wid = tid >> 5, lane = tid & 31;
    int b0 = blockIdx.y * BT;
    int v0 = blockIdx.x * VT2;

    unsigned wbase = su32(s_W);

    // stage W chunk 0 first
    stage_w(v0, 0, wbase);
    asm volatile("cp.async.commit_group;" ::: "memory");

    // stage A (pose features, tf32 bits): 32 rows x 224 cols = 1792 float4
#pragma unroll
    for (int it = 0; it < 7; it++) {
        int idx = tid + it * 256;
        int bb = idx / 56, kq = idx - bb * 56;
        float4 f = ((const float4*)(g_F + (size_t)(b0 + bb) * KTOT))[kq];
        *(float4*)(s_A + bb * ASTR + kq * 4) = f;
    }
    // relA duplicated
    {
        const float4* src = (const float4*)(g_relA + (size_t)b0 * (NJ * 24));
        float4* dst = (float4*)s_ra;
#pragma unroll
        for (int it = 0; it < 18; it++) dst[tid + it * 256] = src[tid + it * 256];
    }
    // lbs [24][64]
#pragma unroll
    for (int it = 0; it < 6; it++) {
        int idx = tid + it * 256;
        int j = idx >> 6, vl = idx & 63;
        int v = v0 + vl;
        s_lbs[idx] = (v < NV) ? g_lbsT[j * NV + v] : 0.f;
    }
    // sd planes [30][64]
    for (int idx = tid; idx < 30 * 64; idx += 256) {
        int rr = idx >> 6, vl = idx & 63;
        int v = v0 + vl;
        s_sd[idx] = (v < NV) ? g_sdT[(size_t)rr * NV + v] : 0.f;
    }
    // template [3][64]
    if (tid < 3 * 64) {
        int rr = tid >> 6, vl = tid & 63;
        int v = v0 + vl;
        s_tp[tid] = (v < NV) ? g_tpT[(size_t)rr * NV + v] : 0.f;
    }
    // shape coeffs duplicated [10][32][2] = 320 entries; STRIDED (covers under 256 threads)
    for (int idx = tid; idx < NBETA * BT; idx += 256) {
        int n = idx >> 5, bt = idx & 31;
        float v = inputs[(size_t)(b0 + bt) * INW + 72 + n];
        *(float2*)(s_shd + idx * 2) = make_float2(v, v);
    }

    // ---- pose GEMM: 7 chunks of K=32, double-buffered ----
    int mh = wid & 1, nb = wid >> 1;
    float acc6[6][4];
#pragma unroll
    for (int t = 0; t < 6; t++)
#pragma unroll
        for (int q = 0; q < 4; q++) acc6[t][q] = 0.f;

    int arow = (mh * 16 + (lane >> 2)) * ASTR + (lane & 3);
    int bcol = nb * 48 + (lane >> 2);

    for (int ck = 0; ck < 7; ck++) {
        if (ck + 1 < 7) {
            stage_w(v0, ck + 1, wbase + ((ck + 1) & 1) * (32 * WSTR * 4));
            asm volatile("cp.async.commit_group;" ::: "memory");
            asm volatile("cp.async.wait_group 1;" ::: "memory");
        } else {
            asm volatile("cp.async.wait_group 0;" ::: "memory");
        }
        __syncthreads();
        const float* W = s_W + (ck & 1) * (32 * WSTR);
#pragma unroll
        for (int ks = 0; ks < 4; ks++) {
            int ka = ck * 32 + ks * 8;
            uint32_t a0 = __float_as_uint(s_A[arow + ka]);
            uint32_t a1 = __float_as_uint(s_A[arow + 8 * ASTR + ka]);
            uint32_t a2 = __float_as_uint(s_A[arow + ka + 4]);
            uint32_t a3 = __float_as_uint(s_A[arow + 8 * ASTR + ka + 4]);
            int bro = (ks * 8 + (lane & 3)) * WSTR + bcol;
#pragma unroll
            for (int t = 0; t < 6; t++) {
                uint32_t bb0 = __float_as_uint(W[bro + t * 8]);
                uint32_t bb1 = __float_as_uint(W[bro + 4 * WSTR + t * 8]);
                mma_tf32(acc6[t], a0, a1, a2, a3, bb0, bb1);
            }
        }
        __syncthreads();
    }

    // ---- store D tiles to s_vp ----
    {
        int r0 = mh * 16 + (lane >> 2);
        int cb = nb * 48 + (lane & 3) * 2;
#pragma unroll
        for (int t = 0; t < 6; t++) {
            *(float2*)(s_vp + r0 * VPSTR + cb + t * 8)       = make_float2(acc6[t][0], acc6[t][1]);
            *(float2*)(s_vp + (r0 + 8) * VPSTR + cb + t * 8) = make_float2(acc6[t][2], acc6[t][3]);
        }
    }
    __syncthreads();

    // ---- shape blend + template + LBS (4 batches x 1 vertex pair per thread) ----
    int p = lane;
    int bb0 = wid * 4;

    u64 acc[4][3];
    {
        u64 t2[3];
#pragma unroll
        for (int c = 0; c < 3; c++) t2[c] = *(const u64*)(s_tp + c * 64 + 2 * p);
#pragma unroll
        for (int b = 0; b < 4; b++)
#pragma unroll
            for (int c = 0; c < 3; c++)
                acc[b][c] = add2(*(const u64*)(s_vp + (bb0 + b) * VPSTR + c * 64 + 2 * p), t2[c]);
#pragma unroll
        for (int n = 0; n < NBETA; n++) {
            u64 sd2[3];
#pragma unroll
            for (int c = 0; c < 3; c++)
                sd2[c] = *(const u64*)(s_sd + (n * 3 + c) * 64 + 2 * p);
#pragma unroll
            for (int b = 0; b < 4; b++) {
                u64 sh2 = *(const u64*)(s_shd + (n * 32 + bb0 + b) * 2);
#pragma unroll
                for (int c = 0; c < 3; c++)
                    acc[b][c] = ffma2(sh2, sd2[c], acc[b][c]);
            }
        }
    }

    u64 o[4][3];
#pragma unroll
    for (int b = 0; b < 4; b++)
#pragma unroll
        for (int c = 0; c < 3; c++) o[b][c] = 0ull;

    for (int j = 0; j < NJ; j++) {
        u64 w2 = *(const u64*)(s_lbs + j * 64 + 2 * p);
#pragma unroll
        for (int b = 0; b < 4; b++) {
            const float* A = s_ra + ((size_t)(bb0 + b) * NJ + j) * 24;
            u64 x = acc[b][0], y = acc[b][1], z = acc[b][2], t;
            {
                U4 u0; u0.q = *(const uint4*)(A);
                U4 u1; u1.q = *(const uint4*)(A + 4);
                t = ffma2(u0.h[0], x, u1.h[1]);
                t = ffma2(u0.h[1], y, t);
                t = ffma2(u1.h[0], z, t);
                o[b][0] = ffma2(w2, t, o[b][0]);
            }
            {
                U4 u0; u0.q = *(const uint4*)(A + 8);
                U4 u1; u1.q = *(const uint4*)(A + 12);
                t = ffma2(u0.h[0], x, u1.h[1]);
                t = ffma2(u0.h[1], y, t);
                t = ffma2(u1.h[0], z, t);
                o[b][1] = ffma2(w2, t, o[b][1]);
            }
            {
                U4 u0; u0.q = *(const uint4*)(A + 16);
                U4 u1; u1.q = *(const uint4*)(A + 20);
                t = ffma2(u0.h[0], x, u1.h[1]);
                t = ffma2(u0.h[1], y, t);
                t = ffma2(u1.h[0], z, t);
                o[b][2] = ffma2(w2, t, o[b][2]);
            }
        }
    }

    int v1 = v0 + 2 * p;
    if (v1 < NV) {
#pragma unroll
        for (int b = 0; b < 4; b++) {
            size_t bg = b0 + bb0 + b;
            float xa, xb, ya, yb, za, zb;
            unpk(o[b][0], xa, xb); unpk(o[b][1], ya, yb); unpk(o[b][2], za, zb);
            float* d = outV + (bg * NV + v1) * 3;
            *(float2*)(d)     = make_float2(xa, ya);
            *(float2*)(d + 2) = make_float2(za, xb);
            *(float2*)(d + 4) = make_float2(yb, zb);
        }
    }
}

// =====================================================================
// K3: joints — 2 batches per block, batch dim packed
// =====================================================================
__global__ void __launch_bounds__(256)
k3_joints(const float* __restrict__ verts, float* __restrict__ outJ)
{
    int b0 = blockIdx.x * 2, tid = threadIdx.x;
    u64 acc[NK * 3];
#pragma unroll
    for (int t = 0; t < NK * 3; t++) acc[t] = 0ull;

    for (int v = tid; v < NV; v += 256) {
        const float* pA = verts + ((size_t)b0 * NV + v) * 3;
        const float* pB = pA + (size_t)NV * 3;
        u64 px = pack2(pA[0], pB[0]);
        u64 py = pack2(pA[1], pB[1]);
        u64 pz = pack2(pA[2], pB[2]);
#pragma unroll
        for (int k = 0; k < NK; k++) {
            float r = g_jregT[k * NV + v];
            u64 r2 = pack2(r, r);
            acc[k * 3 + 0] = ffma2(r2, px, acc[k * 3 + 0]);
            acc[k * 3 + 1] = ffma2(r2, py, acc[k * 3 + 1]);
            acc[k * 3 + 2] = ffma2(r2, pz, acc[k * 3 + 2]);
        }
    }
    __shared__ u64 sred[8][NK * 3];
    int lane = tid & 31, wid = tid >> 5;
#pragma unroll
    for (int t = 0; t < NK * 3; t++) {
        float lo, hi;
        unpk(acc[t], lo, hi);
#pragma unroll
        for (int off = 16; off > 0; off >>= 1) {
            lo += __shfl_down_sync(0xFFFFFFFFu, lo, off);
            hi += __shfl_down_sync(0xFFFFFFFFu, hi, off);
        }
        if (lane == 0) sred[wid][t] = pack2(lo, hi);
    }
    __syncthreads();
    if (tid < NK * 3) {
        float slo = 0.f, shi = 0.f;
#pragma unroll
        for (int w = 0; w < 8; w++) {
            float lo, hi; unpk(sred[w][tid], lo, hi);
            slo += lo; shi += hi;
        }
        outJ[(size_t)b0 * (NK * 3) + tid] = slo;
        outJ[(size_t)(b0 + 1) * (NK * 3) + tid] = shi;
    }
}

// =====================================================================
extern "C" void kernel_launch(void* const* d_in, const int* in_sizes, int n_in,
                              void* d_out, int out_size)
{
    const float* inputs = (const float*)d_in[0];
    const float* vtempl = (const float*)d_in[1];
    const float* sdirs  = (const float*)d_in[2];
    const float* jreg24 = (const float*)d_in[3];
    const float* pdirs  = (const float*)d_in[4];
    const float* lbsw   = (const float*)d_in[5];
    const float* jreg19 = (const float*)d_in[6];

    float* out   = (float*)d_out;
    float* outV  = out;
    float* outJ  = outV + (size_t)BN * NV * 3;
    float* outRs = outJ + (size_t)BN * NK * 3;

    size_t k2_smem = (size_t)SMEM_FLOATS * sizeof(float); // 196864 B
    cudaFuncSetAttribute(k2_main, cudaFuncAttributeMaxDynamicSharedMemorySize, (int)k2_smem);

    k0a_jointdirs<<<NJ * 3, 256>>>(vtempl, sdirs, jreg24);
    k0w_build<<<KTOT * 3, 256>>>(pdirs);
    k0t1b_planes<<<NBETA * 3 + 3, 256>>>(sdirs, vtempl);
    k0t2_regs<<<(NV * NK + NV * NJ + 255) / 256, 256>>>(jreg19, lbsw);
    k1_batchprep<<<BN, 128>>>(inputs, outRs);
    dim3 g2((NV + VT2 - 1) / VT2, BN / BT);
    k2_main<<<g2, 256, k2_smem>>>(inputs, outV);
    k3_joints<<<BN / 2, 256>>>(outV, outJ);
}

// round 15
// speedup vs baseline: 3.1679x; 1.1141x over previous
#include <cuda_runtime.h>
#include <math.h>
#include <stdint.h>

#define BN 1024
#define NV 6890
#define NVP 6912
#define NV3 20670
#define NJ 24
#define NBETA 10
#define NP 207
#define NK 19
#define INW 82

#define KTOT 224
#define BT 32
#define VT2 64
#define ASTR 228
#define WSTR 200
#define VPSTR 200
#define RELB_STR 384      // 24*16 per batch
#define LBS_STR 28
#define TSTR 66
#define TSLOT 1056        // 16*66

typedef unsigned long long u64;

// ---- device scratch ----
__device__ float g_Jdirs[NBETA * NJ * 3];
__device__ float g_Jtmpl[NJ * 3];
__device__ float g_jregT[NK * NV];
__device__ float g_sdT[NBETA * 3 * NV];
__device__ float g_tpT[3 * NV];
__device__ __align__(16) float g_W[KTOT * 3 * NVP];   // tf32 pose dirs planes
__device__ __align__(16) float g_F[BN * KTOT];        // tf32 pose features
__device__ __align__(16) float g_relA[BN * RELB_STR]; // [b][j][16] fp32 (cols 12..15 = 0)

__constant__ int c_parents[NJ] = {0,0,0,0,1,2,3,4,5,6,7,8,9,9,9,12,13,14,16,17,18,19,20,21};

// ---- helpers ----
__device__ __forceinline__ u64 ffma2(u64 a, u64 b, u64 c) {
    u64 d; asm("fma.rn.f32x2 %0, %1, %2, %3;" : "=l"(d) : "l"(a), "l"(b), "l"(c)); return d;
}
__device__ __forceinline__ u64 add2(u64 a, u64 b) {
    u64 d; asm("add.rn.f32x2 %0, %1, %2;" : "=l"(d) : "l"(a), "l"(b)); return d;
}
__device__ __forceinline__ u64 pack2(float a, float b) {
    u64 r; asm("mov.b64 %0, {%1, %2};" : "=l"(r) : "f"(a), "f"(b)); return r;
}
__device__ __forceinline__ void unpk(u64 v, float& a, float& b) {
    asm("mov.b64 {%0, %1}, %2;" : "=f"(a), "=f"(b) : "l"(v));
}
__device__ __forceinline__ float to_tf32(float x) {
    uint32_t u; asm("cvt.rna.tf32.f32 %0, %1;" : "=r"(u) : "f"(x));
    return __uint_as_float(u);
}
__device__ __forceinline__ void mma_tf32(float* d, uint32_t a0, uint32_t a1,
                                         uint32_t a2, uint32_t a3,
                                         uint32_t b0, uint32_t b1) {
    asm volatile("mma.sync.aligned.m16n8k8.row.col.f32.tf32.tf32.f32 "
                 "{%0,%1,%2,%3}, {%4,%5,%6,%7}, {%8,%9}, {%0,%1,%2,%3};"
                 : "+f"(d[0]), "+f"(d[1]), "+f"(d[2]), "+f"(d[3])
                 : "r"(a0), "r"(a1), "r"(a2), "r"(a3), "r"(b0), "r"(b1));
}
union U4 { uint4 q; u64 h[2]; };
__device__ __forceinline__ unsigned su32(const void* p) {
    return (unsigned)__cvta_generic_to_shared(p);
}

// =====================================================================
// K0a: fold smpl_j_regressor into shapedirs/template
// =====================================================================
__global__ void k0a_jointdirs(const float* __restrict__ tmpl,
                              const float* __restrict__ sdirs,
                              const float* __restrict__ jreg)
{
    int k = blockIdx.x / 3, c = blockIdx.x % 3;
    float acc[NBETA + 1];
#pragma unroll
    for (int t = 0; t <= NBETA; t++) acc[t] = 0.f;
    for (int v = threadIdx.x; v < NV; v += 256) {
        float r = jreg[v * NJ + k];
        acc[0] += tmpl[v * 3 + c] * r;
#pragma unroll
        for (int n = 0; n < NBETA; n++)
            acc[1 + n] += sdirs[n * NV3 + v * 3 + c] * r;
    }
    __shared__ float red[256];
    for (int t = 0; t <= NBETA; t++) {
        __syncthreads();
        red[threadIdx.x] = acc[t];
        __syncthreads();
        for (int s = 128; s > 0; s >>= 1) {
            if (threadIdx.x < s) red[threadIdx.x] += red[threadIdx.x + s];
            __syncthreads();
        }
        if (threadIdx.x == 0) {
            if (t == 0) g_Jtmpl[k * 3 + c] = red[0];
            else        g_Jdirs[(t - 1) * (NJ * 3) + k * 3 + c] = red[0];
        }
    }
}

// =====================================================================
// K0w: tf32 weight planes g_W[k][c][NVP]
// =====================================================================
__global__ void k0w_build(const float* __restrict__ pdirs)
{
    int r = blockIdx.x;
    int k = r / 3, c = r - 3 * k;
    float* dst = g_W + (size_t)r * NVP;
    if (k < NP) {
        const float* src = pdirs + (size_t)k * NV3 + c;
        for (int v = threadIdx.x; v < NVP; v += 256)
            dst[v] = (v < NV) ? to_tf32(src[3 * v]) : 0.f;
    } else {
        for (int v = threadIdx.x; v < NVP; v += 256) dst[v] = 0.f;
    }
}

// K0t1b: sdT / tpT channel planes (fp32)
__global__ void k0t1b_planes(const float* __restrict__ sdirs,
                             const float* __restrict__ tmpl)
{
    int r = blockIdx.x;
    if (r < NBETA * 3) {
        int n = r / 3, c = r - 3 * n;
        const float* src = sdirs + (size_t)n * NV3 + c;
        float* dst = g_sdT + (size_t)r * NV;
        for (int v = threadIdx.x; v < NV; v += 256) dst[v] = src[3 * v];
    } else {
        int c = r - NBETA * 3;
        float* dst = g_tpT + (size_t)c * NV;
        for (int v = threadIdx.x; v < NV; v += 256) dst[v] = tmpl[3 * v + c];
    }
}

// K0t2: transpose joint_regressor only
__global__ void k0t2_regs(const float* __restrict__ jr)
{
    int idx = blockIdx.x * blockDim.x + threadIdx.x;
    if (idx < NV * NK) {
        int v = idx / NK, k = idx - v * NK;
        g_jregT[k * NV + v] = jr[idx];
    }
}

// =====================================================================
// K1: per-batch rotations, tf32 pose features, chain, relA [b][j][16]
// =====================================================================
__global__ void k1_batchprep(const float* __restrict__ inputs,
                             float* __restrict__ outRs)
{
    int b = blockIdx.x;
    int tid = threadIdx.x;
    __shared__ float sR[NJ][9];
    __shared__ float sJ[NJ][3];
    __shared__ float sG[NJ][12];

    if (tid < NJ) {
        const float* aa = inputs + (size_t)b * INW + tid * 3;
        float x = aa[0], y = aa[1], z = aa[2];
        float ang = sqrtf(x * x + y * y + z * z + 1e-8f);
        float inv = 1.f / ang;
        x *= inv; y *= inv; z *= inv;
        float cc = cosf(ang), ss = sinf(ang), C = 1.f - cc;
        float R[9];
        R[0] = cc + C * x * x;     R[1] = C * x * y - ss * z; R[2] = C * x * z + ss * y;
        R[3] = C * x * y + ss * z; R[4] = cc + C * y * y;     R[5] = C * y * z - ss * x;
        R[6] = C * x * z - ss * y; R[7] = C * y * z + ss * x; R[8] = cc + C * z * z;
#pragma unroll
        for (int e = 0; e < 9; e++) {
            sR[tid][e] = R[e];
            outRs[(size_t)b * (NJ * 9) + tid * 9 + e] = R[e];
        }
    }
    __syncthreads();

    for (int idx = tid; idx < KTOT; idx += 128) {
        float val = 0.f;
        if (idx < NP) {
            int j = 1 + idx / 9, e = idx % 9;
            float d = (e == 0 || e == 4 || e == 8) ? 1.f : 0.f;
            val = to_tf32(sR[j][e] - d);
        }
        g_F[(size_t)b * KTOT + idx] = val;
    }

    if (tid < NJ) {
        const float* shp = inputs + (size_t)b * INW + 72;
#pragma unroll
        for (int c = 0; c < 3; c++) {
            float v = g_Jtmpl[tid * 3 + c];
#pragma unroll
            for (int n = 0; n < NBETA; n++)
                v += shp[n] * g_Jdirs[n * (NJ * 3) + tid * 3 + c];
            sJ[tid][c] = v;
        }
    }
    __syncthreads();

    if (tid < 12) {
        int r = tid / 4, col = tid % 4;
        sG[0][r * 4 + col] = (col < 3) ? sR[0][r * 3 + col] : sJ[0][r];
        for (int i = 1; i < NJ; i++) {
            __syncwarp(0xFFFu);
            int p = c_parents[i];
            float v;
            if (col < 3) {
                v = sG[p][r * 4 + 0] * sR[i][0 * 3 + col]
                  + sG[p][r * 4 + 1] * sR[i][1 * 3 + col]
                  + sG[p][r * 4 + 2] * sR[i][2 * 3 + col];
            } else {
                float t0 = sJ[i][0] - sJ[p][0];
                float t1 = sJ[i][1] - sJ[p][1];
                float t2 = sJ[i][2] - sJ[p][2];
                v = sG[p][r * 4 + 0] * t0 + sG[p][r * 4 + 1] * t1
                  + sG[p][r * 4 + 2] * t2 + sG[p][r * 4 + 3];
            }
            sG[i][r * 4 + col] = v;
        }
        __syncwarp(0xFFFu);
    }
    __syncthreads();

    // relA as [b][j][16] fp32, cols 12..15 zero
    for (int idx = tid; idx < NJ * 16; idx += 128) {
        int j = idx >> 4, c16 = idx & 15;
        float v = 0.f;
        if (c16 < 12) {
            int r = c16 >> 2, col = c16 & 3;
            if (col < 3) v = sG[j][r * 4 + col];
            else v = sG[j][r * 4 + 3]
                   - (sG[j][r * 4 + 0] * sJ[j][0] + sG[j][r * 4 + 1] * sJ[j][1]
                    + sG[j][r * 4 + 2] * sJ[j][2]);
        }
        g_relA[(size_t)b * RELB_STR + idx] = v;
    }
}

// =====================================================================
// K2: tf32 mma pose GEMM + shape blend + tf32 mma LBS
// 256 threads = 8 warps
// =====================================================================
#define OFF_A    0                      // 32*228 = 7296 (later overlaid by s_T)
#define OFF_W    7296                   // 2*32*200 = 12800 (overlaid by s_T)
#define OFF_VP   20096                  // 32*200 = 6400 (v_posed)
#define OFF_RB   26496                  // 32*384 = 12288 (relA tf32)
#define OFF_LB   38784                  // 64*28 = 1792 (lbs tf32)
#define OFF_SD   40576                  // 30*64 = 1920
#define OFF_TP   42496                  // 3*64 = 192
#define OFF_SHD  42688                  // 10*32*2 = 640
#define SMEM_FLOATS 43328               // 173312 bytes

__device__ __forceinline__ void stage_w(int v0, int ck, unsigned dstb)
{
    int tid = threadIdx.x;
#pragma unroll
    for (int it = 0; it < 6; it++) {
        int idx = tid + it * 256;
        int kk = idx / 48, rem = idx - kk * 48;
        int c = rem >> 4, q = rem & 15;
        const float* src = g_W + ((size_t)(ck * 32 + kk) * 3 + c) * NVP + v0 + q * 4;
        unsigned dst = dstb + (kk * WSTR + c * 64 + q * 4) * 4;
        asm volatile("cp.async.ca.shared.global [%0], [%1], 16;"
                     :: "r"(dst), "l"(src) : "memory");
    }
}

__global__ void __launch_bounds__(256, 1)
k2_main(const float* __restrict__ inputs,
        const float* __restrict__ lbsw,
        float* __restrict__ outV)
{
    extern __shared__ float s[];
    float* s_A   = s + OFF_A;
    float* s_W   = s + OFF_W;
    float* s_vp  = s + OFF_VP;
    float* s_rb  = s + OFF_RB;
    float* s_lb  = s + OFF_LB;
    float* s_sd  = s + OFF_SD;
    float* s_tp  = s + OFF_TP;
    float* s_shd = s + OFF_SHD;
    float* s_T   = s + OFF_A;           // overlays s_A/s_W after pose GEMM

    int tid = threadIdx.x;
    int wid = tid >> 5, lane = tid & 31;
    int b0 = blockIdx.y * BT;
    int v0 = blockIdx.x * VT2;

    unsigned wbase = su32(s_W);

    stage_w(v0, 0, wbase);
    asm volatile("cp.async.commit_group;" ::: "memory");

    // A (pose features tf32)
#pragma unroll
    for (int it = 0; it < 7; it++) {
        int idx = tid + it * 256;
        int bb = idx / 56, kq = idx - bb * 56;
        float4 f = ((const float4*)(g_F + (size_t)(b0 + bb) * KTOT))[kq];
        *(float4*)(s_A + bb * ASTR + kq * 4) = f;
    }
    // relB: fp32 -> tf32
#pragma unroll
    for (int it = 0; it < 12; it++) {
        int i4 = tid + it * 256;
        float4 f = ((const float4*)(g_relA + (size_t)b0 * RELB_STR))[i4];
        f.x = to_tf32(f.x); f.y = to_tf32(f.y);
        f.z = to_tf32(f.z); f.w = to_tf32(f.w);
        ((float4*)s_rb)[i4] = f;
    }
    // lbs tf32 [64][28]
    for (int idx = tid; idx < 64 * 24; idx += 256) {
        int vl = idx / 24, j = idx - vl * 24;
        int v = v0 + vl;
        s_lb[vl * LBS_STR + j] = (v < NV) ? to_tf32(lbsw[(size_t)v * NJ + j]) : 0.f;
    }
    // sd planes [30][64]
    for (int idx = tid; idx < 30 * 64; idx += 256) {
        int rr = idx >> 6, vl = idx & 63;
        int v = v0 + vl;
        s_sd[idx] = (v < NV) ? g_sdT[(size_t)rr * NV + v] : 0.f;
    }
    // template [3][64]
    if (tid < 3 * 64) {
        int rr = tid >> 6, vl = tid & 63;
        int v = v0 + vl;
        s_tp[tid] = (v < NV) ? g_tpT[(size_t)rr * NV + v] : 0.f;
    }
    // shape coeffs duplicated [10][32][2]
    for (int idx = tid; idx < NBETA * BT; idx += 256) {
        int n = idx >> 5, bt = idx & 31;
        float v = inputs[(size_t)(b0 + bt) * INW + 72 + n];
        *(float2*)(s_shd + idx * 2) = make_float2(v, v);
    }

    // ---- pose GEMM: 7 chunks of K=32, double-buffered ----
    int mh = wid & 1, nb2 = wid >> 1;
    float acc6[6][4];
#pragma unroll
    for (int t = 0; t < 6; t++)
#pragma unroll
        for (int q = 0; q < 4; q++) acc6[t][q] = 0.f;

    int arow = (mh * 16 + (lane >> 2)) * ASTR + (lane & 3);
    int bcol = nb2 * 48 + (lane >> 2);

    for (int ck = 0; ck < 7; ck++) {
        if (ck + 1 < 7) {
            stage_w(v0, ck + 1, wbase + ((ck + 1) & 1) * (32 * WSTR * 4));
            asm volatile("cp.async.commit_group;" ::: "memory");
            asm volatile("cp.async.wait_group 1;" ::: "memory");
        } else {
            asm volatile("cp.async.wait_group 0;" ::: "memory");
        }
        __syncthreads();
        const float* W = s_W + (ck & 1) * (32 * WSTR);
#pragma unroll
        for (int ks = 0; ks < 4; ks++) {
            int ka = ck * 32 + ks * 8;
            uint32_t a0 = __float_as_uint(s_A[arow + ka]);
            uint32_t a1 = __float_as_uint(s_A[arow + 8 * ASTR + ka]);
            uint32_t a2 = __float_as_uint(s_A[arow + ka + 4]);
            uint32_t a3 = __float_as_uint(s_A[arow + 8 * ASTR + ka + 4]);
            int bro = (ks * 8 + (lane & 3)) * WSTR + bcol;
#pragma unroll
            for (int t = 0; t < 6; t++) {
                uint32_t bb0 = __float_as_uint(W[bro + t * 8]);
                uint32_t bb1 = __float_as_uint(W[bro + 4 * WSTR + t * 8]);
                mma_tf32(acc6[t], a0, a1, a2, a3, bb0, bb1);
            }
        }
        __syncthreads();
    }

    // ---- store pose D to s_vp ----
    {
        int r0 = mh * 16 + (lane >> 2);
        int cb = nb2 * 48 + (lane & 3) * 2;
#pragma unroll
        for (int t = 0; t < 6; t++) {
            *(float2*)(s_vp + r0 * VPSTR + cb + t * 8)       = make_float2(acc6[t][0], acc6[t][1]);
            *(float2*)(s_vp + (r0 + 8) * VPSTR + cb + t * 8) = make_float2(acc6[t][2], acc6[t][3]);
        }
    }
    __syncthreads();

    // ---- v_posed = poseD + template + shape blend (in place, packed) ----
    {
        int p = lane;
        int bb0 = wid * 4;
        u64 acc[4][3];
        u64 t2[3];
#pragma unroll
        for (int c = 0; c < 3; c++) t2[c] = *(const u64*)(s_tp + c * 64 + 2 * p);
#pragma unroll
        for (int b = 0; b < 4; b++)
#pragma unroll
            for (int c = 0; c < 3; c++)
                acc[b][c] = add2(*(const u64*)(s_vp + (bb0 + b) * VPSTR + c * 64 + 2 * p), t2[c]);
#pragma unroll
        for (int n = 0; n < NBETA; n++) {
            u64 sd2[3];
#pragma unroll
            for (int c = 0; c < 3; c++)
                sd2[c] = *(const u64*)(s_sd + (n * 3 + c) * 64 + 2 * p);
#pragma unroll
            for (int b = 0; b < 4; b++) {
                u64 sh2 = *(const u64*)(s_shd + (n * 32 + bb0 + b) * 2);
#pragma unroll
                for (int c = 0; c < 3; c++)
                    acc[b][c] = ffma2(sh2, sd2[c], acc[b][c]);
            }
        }
#pragma unroll
        for (int b = 0; b < 4; b++)
#pragma unroll
            for (int c = 0; c < 3; c++)
                *(u64*)(s_vp + (bb0 + b) * VPSTR + c * 64 + 2 * lane) = acc[b][c];
    }
    __syncthreads();   // v_posed complete; s_A/s_W now dead -> s_T usable

    // ---- LBS via tensor cores: T = lbs(tf32) @ relA(tf32) ----
    uint32_t afr[4][3][4];
#pragma unroll
    for (int mt = 0; mt < 4; mt++)
#pragma unroll
        for (int ks = 0; ks < 3; ks++) {
            int ar = (mt * 16 + (lane >> 2)) * LBS_STR + ks * 8 + (lane & 3);
            afr[mt][ks][0] = __float_as_uint(s_lb[ar]);
            afr[mt][ks][1] = __float_as_uint(s_lb[ar + 8 * LBS_STR]);
            afr[mt][ks][2] = __float_as_uint(s_lb[ar + 4]);
            afr[mt][ks][3] = __float_as_uint(s_lb[ar + 8 * LBS_STR + 4]);
        }

    int p = lane;
    int v1 = v0 + 2 * p;

    for (int ph = 0; ph < 2; ph++) {
#pragma unroll
        for (int lb = 0; lb < 2; lb++) {
            int lbat = ph * 16 + wid * 2 + lb;          // 0..31 local batch
            const float* B = s_rb + lbat * RELB_STR;
            float la[4][2][4];
#pragma unroll
            for (int mt = 0; mt < 4; mt++)
#pragma unroll
                for (int nb = 0; nb < 2; nb++)
#pragma unroll
                    for (int q = 0; q < 4; q++) la[mt][nb][q] = 0.f;
#pragma unroll
            for (int ks = 0; ks < 3; ks++) {
#pragma unroll
                for (int nb = 0; nb < 2; nb++) {
                    int bro = (ks * 8 + (lane & 3)) * 16 + nb * 8 + (lane >> 2);
                    uint32_t bb0 = __float_as_uint(B[bro]);
                    uint32_t bb1 = __float_as_uint(B[bro + 64]);
#pragma unroll
                    for (int mt = 0; mt < 4; mt++)
                        mma_tf32(la[mt][nb], afr[mt][ks][0], afr[mt][ks][1],
                                 afr[mt][ks][2], afr[mt][ks][3], bb0, bb1);
                }
            }
            // store transposed: s_T[slot][n][v], slot = wid*2+lb
            float* Ts = s_T + (wid * 2 + lb) * TSLOT;
            int r0 = (lane >> 2);
            int c0 = 2 * (lane & 3);
#pragma unroll
            for (int mt = 0; mt < 4; mt++)
#pragma unroll
                for (int nb = 0; nb < 2; nb++) {
                    int n0 = nb * 8 + c0;
                    int rr = mt * 16 + r0;
                    Ts[n0 * TSTR + rr]           = la[mt][nb][0];
                    Ts[(n0 + 1) * TSTR + rr]     = la[mt][nb][1];
                    Ts[n0 * TSTR + rr + 8]       = la[mt][nb][2];
                    Ts[(n0 + 1) * TSTR + rr + 8] = la[mt][nb][3];
                }
        }
        __syncwarp();
        // epilogue: apply T to v_posed, write out (warp-local batches)
#pragma unroll
        for (int lb = 0; lb < 2; lb++) {
            int lbat = ph * 16 + wid * 2 + lb;
            const float* Ts = s_T + (wid * 2 + lb) * TSLOT;
            u64 x2 = *(const u64*)(s_vp + lbat * VPSTR + 2 * p);
            u64 y2 = *(const u64*)(s_vp + lbat * VPSTR + 64 + 2 * p);
            u64 z2 = *(const u64*)(s_vp + lbat * VPSTR + 128 + 2 * p);
            u64 T0 = *(const u64*)(Ts + 0 * TSTR + 2 * p);
            u64 T1 = *(const u64*)(Ts + 1 * TSTR + 2 * p);
            u64 T2 = *(const u64*)(Ts + 2 * TSTR + 2 * p);
            u64 T3 = *(const u64*)(Ts + 3 * TSTR + 2 * p);
            u64 ox = ffma2(T0, x2, ffma2(T1, y2, ffma2(T2, z2, T3)));
            T0 = *(const u64*)(Ts + 4 * TSTR + 2 * p);
            T1 = *(const u64*)(Ts + 5 * TSTR + 2 * p);
            T2 = *(const u64*)(Ts + 6 * TSTR + 2 * p);
            T3 = *(const u64*)(Ts + 7 * TSTR + 2 * p);
            u64 oy = ffma2(T0, x2, ffma2(T1, y2, ffma2(T2, z2, T3)));
            T0 = *(const u64*)(Ts + 8 * TSTR + 2 * p);
            T1 = *(const u64*)(Ts + 9 * TSTR + 2 * p);
            T2 = *(const u64*)(Ts + 10 * TSTR + 2 * p);
            T3 = *(const u64*)(Ts + 11 * TSTR + 2 * p);
            u64 oz = ffma2(T0, x2, ffma2(T1, y2, ffma2(T2, z2, T3)));
            if (v1 < NV) {
                float xa, xb, ya, yb, za, zb;
                unpk(ox, xa, xb); unpk(oy, ya, yb); unpk(oz, za, zb);
                float* d = outV + ((size_t)(b0 + lbat) * NV + v1) * 3;
                *(float2*)(d)     = make_float2(xa, ya);
                *(float2*)(d + 2) = make_float2(za, xb);
                *(float2*)(d + 4) = make_float2(yb, zb);
            }
        }
        __syncwarp();
    }
}

// =====================================================================
// K3: joints — 2 batches per block, batch dim packed
// =====================================================================
__global__ void __launch_bounds__(256)
k3_joints(const float* __restrict__ verts, float* __restrict__ outJ)
{
    int b0 = blockIdx.x * 2, tid = threadIdx.x;
    u64 acc[NK * 3];
#pragma unroll
    for (int t = 0; t < NK * 3; t++) acc[t] = 0ull;

    for (int v = tid; v < NV; v += 256) {
        const float* pA = verts + ((size_t)b0 * NV + v) * 3;
        const float* pB = pA + (size_t)NV * 3;
        u64 px = pack2(pA[0], pB[0]);
        u64 py = pack2(pA[1], pB[1]);
        u64 pz = pack2(pA[2], pB[2]);
#pragma unroll
        for (int k = 0; k < NK; k++) {
            float r = g_jregT[k * NV + v];
            u64 r2 = pack2(r, r);
            acc[k * 3 + 0] = ffma2(r2, px, acc[k * 3 + 0]);
            acc[k * 3 + 1] = ffma2(r2, py, acc[k * 3 + 1]);
            acc[k * 3 + 2] = ffma2(r2, pz, acc[k * 3 + 2]);
        }
    }
    __shared__ u64 sred[8][NK * 3];
    int lane = tid & 31, wid = tid >> 5;
#pragma unroll
    for (int t = 0; t < NK * 3; t++) {
        float lo, hi;
        unpk(acc[t], lo, hi);
#pragma unroll
        for (int off = 16; off > 0; off >>= 1) {
            lo += __shfl_down_sync(0xFFFFFFFFu, lo, off);
            hi += __shfl_down_sync(0xFFFFFFFFu, hi, off);
        }
        if (lane == 0) sred[wid][t] = pack2(lo, hi);
    }
    __syncthreads();
    if (tid < NK * 3) {
        float slo = 0.f, shi = 0.f;
#pragma unroll
        for (int w = 0; w < 8; w++) {
            float lo, hi; unpk(sred[w][tid], lo, hi);
            slo += lo; shi += hi;
        }
        outJ[(size_t)b0 * (NK * 3) + tid] = slo;
        outJ[(size_t)(b0 + 1) * (NK * 3) + tid] = shi;
    }
}

// =====================================================================
extern "C" void kernel_launch(void* const* d_in, const int* in_sizes, int n_in,
                              void* d_out, int out_size)
{
    const float* inputs = (const float*)d_in[0];
    const float* vtempl = (const float*)d_in[1];
    const float* sdirs  = (const float*)d_in[2];
    const float* jreg24 = (const float*)d_in[3];
    const float* pdirs  = (const float*)d_in[4];
    const float* lbsw   = (const float*)d_in[5];
    const float* jreg19 = (const float*)d_in[6];

    float* out   = (float*)d_out;
    float* outV  = out;
    float* outJ  = outV + (size_t)BN * NV * 3;
    float* outRs = outJ + (size_t)BN * NK * 3;

    size_t k2_smem = (size_t)SMEM_FLOATS * sizeof(float); // 173312 B
    cudaFuncSetAttribute(k2_main, cudaFuncAttributeMaxDynamicSharedMemorySize, (int)k2_smem);

    k0a_jointdirs<<<NJ * 3, 256>>>(vtempl, sdirs, jreg24);
    k0w_build<<<KTOT * 3, 256>>>(pdirs);
    k0t1b_planes<<<NBETA * 3 + 3, 256>>>(sdirs, vtempl);
    k0t2_regs<<<(NV * NK + 255) / 256, 256>>>(jreg19);
    k1_batchprep<<<BN, 128>>>(inputs, outRs);
    dim3 g2((NV + VT2 - 1) / VT2, BN / BT);
    k2_main<<<g2, 256, k2_smem>>>(inputs, lbsw, outV);
    k3_joints<<<BN / 2, 256>>>(outV, outJ);
}

// round 16
// speedup vs baseline: 3.1706x; 1.0009x over previous
#include <cuda_runtime.h>
#include <math.h>
#include <stdint.h>

#define BN 1024
#define NV 6890
#define NVP 6912
#define NV3 20670
#define NJ 24
#define NBETA 10
#define NP 207
#define NK 19
#define INW 82

#define KTOT 224
#define BT 32
#define VT2 64
#define ASTR 228
#define WSTR 200
#define VPSTR 200
#define RELB_STR 384
#define LBS_STR 28
#define TSTR 66
#define TSLOT 1056
#define JSTR 28

typedef unsigned long long u64;

// ---- device scratch ----
__device__ float g_Jdirs[NBETA * NJ * 3];
__device__ float g_Jtmpl[NJ * 3];
__device__ float g_sdT[NBETA * 3 * NV];
__device__ float g_tpT[3 * NV];
__device__ __align__(16) float g_W[KTOT * 3 * NVP];   // tf32 pose dirs planes
__device__ __align__(16) float g_F[BN * KTOT];        // tf32 pose features
__device__ __align__(16) float g_relA[BN * RELB_STR]; // [b][j][16] fp32

__constant__ int c_parents[NJ] = {0,0,0,0,1,2,3,4,5,6,7,8,9,9,9,12,13,14,16,17,18,19,20,21};

// ---- helpers ----
__device__ __forceinline__ u64 ffma2(u64 a, u64 b, u64 c) {
    u64 d; asm("fma.rn.f32x2 %0, %1, %2, %3;" : "=l"(d) : "l"(a), "l"(b), "l"(c)); return d;
}
__device__ __forceinline__ u64 add2(u64 a, u64 b) {
    u64 d; asm("add.rn.f32x2 %0, %1, %2;" : "=l"(d) : "l"(a), "l"(b)); return d;
}
__device__ __forceinline__ u64 pack2(float a, float b) {
    u64 r; asm("mov.b64 %0, {%1, %2};" : "=l"(r) : "f"(a), "f"(b)); return r;
}
__device__ __forceinline__ void unpk(u64 v, float& a, float& b) {
    asm("mov.b64 {%0, %1}, %2;" : "=f"(a), "=f"(b) : "l"(v));
}
__device__ __forceinline__ float to_tf32(float x) {
    uint32_t u; asm("cvt.rna.tf32.f32 %0, %1;" : "=r"(u) : "f"(x));
    return __uint_as_float(u);
}
__device__ __forceinline__ void mma_tf32(float* d, uint32_t a0, uint32_t a1,
                                         uint32_t a2, uint32_t a3,
                                         uint32_t b0, uint32_t b1) {
    asm volatile("mma.sync.aligned.m16n8k8.row.col.f32.tf32.tf32.f32 "
                 "{%0,%1,%2,%3}, {%4,%5,%6,%7}, {%8,%9}, {%0,%1,%2,%3};"
                 : "+f"(d[0]), "+f"(d[1]), "+f"(d[2]), "+f"(d[3])
                 : "r"(a0), "r"(a1), "r"(a2), "r"(a3), "r"(b0), "r"(b1));
}
union U4 { uint4 q; u64 h[2]; };
__device__ __forceinline__ unsigned su32(const void* p) {
    return (unsigned)__cvta_generic_to_shared(p);
}

// =====================================================================
// K0a: fold smpl_j_regressor into shapedirs/template
// =====================================================================
__global__ void k0a_jointdirs(const float* __restrict__ tmpl,
                              const float* __restrict__ sdirs,
                              const float* __restrict__ jreg)
{
    int k = blockIdx.x / 3, c = blockIdx.x % 3;
    float acc[NBETA + 1];
#pragma unroll
    for (int t = 0; t <= NBETA; t++) acc[t] = 0.f;
    for (int v = threadIdx.x; v < NV; v += 256) {
        float r = jreg[v * NJ + k];
        acc[0] += tmpl[v * 3 + c] * r;
#pragma unroll
        for (int n = 0; n < NBETA; n++)
            acc[1 + n] += sdirs[n * NV3 + v * 3 + c] * r;
    }
    __shared__ float red[256];
    for (int t = 0; t <= NBETA; t++) {
        __syncthreads();
        red[threadIdx.x] = acc[t];
        __syncthreads();
        for (int s = 128; s > 0; s >>= 1) {
            if (threadIdx.x < s) red[threadIdx.x] += red[threadIdx.x + s];
            __syncthreads();
        }
        if (threadIdx.x == 0) {
            if (t == 0) g_Jtmpl[k * 3 + c] = red[0];
            else        g_Jdirs[(t - 1) * (NJ * 3) + k * 3 + c] = red[0];
        }
    }
}

// =====================================================================
// K0w: tf32 weight planes g_W[k][c][NVP]
// =====================================================================
__global__ void k0w_build(const float* __restrict__ pdirs)
{
    int r = blockIdx.x;
    int k = r / 3, c = r - 3 * k;
    float* dst = g_W + (size_t)r * NVP;
    if (k < NP) {
        const float* src = pdirs + (size_t)k * NV3 + c;
        for (int v = threadIdx.x; v < NVP; v += 256)
            dst[v] = (v < NV) ? to_tf32(src[3 * v]) : 0.f;
    } else {
        for (int v = threadIdx.x; v < NVP; v += 256) dst[v] = 0.f;
    }
}

// K0t1b: sdT / tpT channel planes (fp32)
__global__ void k0t1b_planes(const float* __restrict__ sdirs,
                             const float* __restrict__ tmpl)
{
    int r = blockIdx.x;
    if (r < NBETA * 3) {
        int n = r / 3, c = r - 3 * n;
        const float* src = sdirs + (size_t)n * NV3 + c;
        float* dst = g_sdT + (size_t)r * NV;
        for (int v = threadIdx.x; v < NV; v += 256) dst[v] = src[3 * v];
    } else {
        int c = r - NBETA * 3;
        float* dst = g_tpT + (size_t)c * NV;
        for (int v = threadIdx.x; v < NV; v += 256) dst[v] = tmpl[3 * v + c];
    }
}

// K0z: zero outJ (poisoned by harness)
__global__ void k0z_zero(float* __restrict__ outJ)
{
    int idx = blockIdx.x * blockDim.x + threadIdx.x;
    if (idx < BN * NK * 3) outJ[idx] = 0.f;
}

// =====================================================================
// K1: per-batch rotations, tf32 pose features, chain, relA [b][j][16]
// =====================================================================
__global__ void k1_batchprep(const float* __restrict__ inputs,
                             float* __restrict__ outRs)
{
    int b = blockIdx.x;
    int tid = threadIdx.x;
    __shared__ float sR[NJ][9];
    __shared__ float sJ[NJ][3];
    __shared__ float sG[NJ][12];

    if (tid < NJ) {
        const float* aa = inputs + (size_t)b * INW + tid * 3;
        float x = aa[0], y = aa[1], z = aa[2];
        float ang = sqrtf(x * x + y * y + z * z + 1e-8f);
        float inv = 1.f / ang;
        x *= inv; y *= inv; z *= inv;
        float cc = cosf(ang), ss = sinf(ang), C = 1.f - cc;
        float R[9];
        R[0] = cc + C * x * x;     R[1] = C * x * y - ss * z; R[2] = C * x * z + ss * y;
        R[3] = C * x * y + ss * z; R[4] = cc + C * y * y;     R[5] = C * y * z - ss * x;
        R[6] = C * x * z - ss * y; R[7] = C * y * z + ss * x; R[8] = cc + C * z * z;
#pragma unroll
        for (int e = 0; e < 9; e++) {
            sR[tid][e] = R[e];
            outRs[(size_t)b * (NJ * 9) + tid * 9 + e] = R[e];
        }
    }
    __syncthreads();

    for (int idx = tid; idx < KTOT; idx += 128) {
        float val = 0.f;
        if (idx < NP) {
            int j = 1 + idx / 9, e = idx % 9;
            float d = (e == 0 || e == 4 || e == 8) ? 1.f : 0.f;
            val = to_tf32(sR[j][e] - d);
        }
        g_F[(size_t)b * KTOT + idx] = val;
    }

    if (tid < NJ) {
        const float* shp = inputs + (size_t)b * INW + 72;
#pragma unroll
        for (int c = 0; c < 3; c++) {
            float v = g_Jtmpl[tid * 3 + c];
#pragma unroll
            for (int n = 0; n < NBETA; n++)
                v += shp[n] * g_Jdirs[n * (NJ * 3) + tid * 3 + c];
            sJ[tid][c] = v;
        }
    }
    __syncthreads();

    if (tid < 12) {
        int r = tid / 4, col = tid % 4;
        sG[0][r * 4 + col] = (col < 3) ? sR[0][r * 3 + col] : sJ[0][r];
        for (int i = 1; i < NJ; i++) {
            __syncwarp(0xFFFu);
            int p = c_parents[i];
            float v;
            if (col < 3) {
                v = sG[p][r * 4 + 0] * sR[i][0 * 3 + col]
                  + sG[p][r * 4 + 1] * sR[i][1 * 3 + col]
                  + sG[p][r * 4 + 2] * sR[i][2 * 3 + col];
            } else {
                float t0 = sJ[i][0] - sJ[p][0];
                float t1 = sJ[i][1] - sJ[p][1];
                float t2 = sJ[i][2] - sJ[p][2];
                v = sG[p][r * 4 + 0] * t0 + sG[p][r * 4 + 1] * t1
                  + sG[p][r * 4 + 2] * t2 + sG[p][r * 4 + 3];
            }
            sG[i][r * 4 + col] = v;
        }
        __syncwarp(0xFFFu);
    }
    __syncthreads();

    for (int idx = tid; idx < NJ * 16; idx += 128) {
        int j = idx >> 4, c16 = idx & 15;
        float v = 0.f;
        if (c16 < 12) {
            int r = c16 >> 2, col = c16 & 3;
            if (col < 3) v = sG[j][r * 4 + col];
            else v = sG[j][r * 4 + 3]
                   - (sG[j][r * 4 + 0] * sJ[j][0] + sG[j][r * 4 + 1] * sJ[j][1]
                    + sG[j][r * 4 + 2] * sJ[j][2]);
        }
        g_relA[(size_t)b * RELB_STR + idx] = v;
    }
}

// =====================================================================
// K2: tf32 mma pose GEMM + shape blend + tf32 mma LBS + fused joints
// =====================================================================
#define OFF_A    0          // 7296 (overlaid by s_T later)
#define OFF_W    7296       // 12800 (overlaid by s_T)
#define OFF_VP   20096      // 6400
#define OFF_RB   26496      // 12288
#define OFF_LB   38784      // 1792
#define OFF_SD   40576      // 1920
#define OFF_TP   42496      // 192
#define OFF_SHD  42688      // 640
#define OFF_JR   43328      // 64*28 = 1792
#define SMEM_FLOATS 45120   // 180480 bytes

__device__ __forceinline__ void stage_w(int v0, int ck, unsigned dstb)
{
    int tid = threadIdx.x;
#pragma unroll
    for (int it = 0; it < 6; it++) {
        int idx = tid + it * 256;
        int kk = idx / 48, rem = idx - kk * 48;
        int c = rem >> 4, q = rem & 15;
        const float* src = g_W + ((size_t)(ck * 32 + kk) * 3 + c) * NVP + v0 + q * 4;
        unsigned dst = dstb + (kk * WSTR + c * 64 + q * 4) * 4;
        asm volatile("cp.async.ca.shared.global [%0], [%1], 16;"
                     :: "r"(dst), "l"(src) : "memory");
    }
}

__global__ void __launch_bounds__(256, 1)
k2_main(const float* __restrict__ inputs,
        const float* __restrict__ lbsw,
        const float* __restrict__ jreg19,
        float* __restrict__ outV,
        float* __restrict__ outJ)
{
    extern __shared__ float s[];
    float* s_A   = s + OFF_A;
    float* s_W   = s + OFF_W;
    float* s_vp  = s + OFF_VP;
    float* s_rb  = s + OFF_RB;
    float* s_lb  = s + OFF_LB;
    float* s_sd  = s + OFF_SD;
    float* s_tp  = s + OFF_TP;
    float* s_shd = s + OFF_SHD;
    float* s_jr  = s + OFF_JR;
    float* s_T   = s + OFF_A;

    int tid = threadIdx.x;
    int wid = tid >> 5, lane = tid & 31;
    int b0 = blockIdx.y * BT;
    int v0 = blockIdx.x * VT2;

    unsigned wbase = su32(s_W);

    stage_w(v0, 0, wbase);
    asm volatile("cp.async.commit_group;" ::: "memory");

    // A (pose features tf32)
#pragma unroll
    for (int it = 0; it < 7; it++) {
        int idx = tid + it * 256;
        int bb = idx / 56, kq = idx - bb * 56;
        float4 f = ((const float4*)(g_F + (size_t)(b0 + bb) * KTOT))[kq];
        *(float4*)(s_A + bb * ASTR + kq * 4) = f;
    }
    // relB: fp32 -> tf32
#pragma unroll
    for (int it = 0; it < 12; it++) {
        int i4 = tid + it * 256;
        float4 f = ((const float4*)(g_relA + (size_t)b0 * RELB_STR))[i4];
        f.x = to_tf32(f.x); f.y = to_tf32(f.y);
        f.z = to_tf32(f.z); f.w = to_tf32(f.w);
        ((float4*)s_rb)[i4] = f;
    }
    // lbs tf32 [64][28]
    for (int idx = tid; idx < 64 * 24; idx += 256) {
        int vl = idx / 24, j = idx - vl * 24;
        int v = v0 + vl;
        s_lb[vl * LBS_STR + j] = (v < NV) ? to_tf32(lbsw[(size_t)v * NJ + j]) : 0.f;
    }
    // jreg19 tf32 [64][28] (pad cols 19..27 zero)
    for (int idx = tid; idx < 64 * JSTR; idx += 256) {
        int vl = idx / JSTR, kk = idx - vl * JSTR;
        int v = v0 + vl;
        s_jr[idx] = (kk < NK && v < NV) ? to_tf32(jreg19[(size_t)v * NK + kk]) : 0.f;
    }
    // sd planes [30][64]
    for (int idx = tid; idx < 30 * 64; idx += 256) {
        int rr = idx >> 6, vl = idx & 63;
        int v = v0 + vl;
        s_sd[idx] = (v < NV) ? g_sdT[(size_t)rr * NV + v] : 0.f;
    }
    // template [3][64]
    if (tid < 3 * 64) {
        int rr = tid >> 6, vl = tid & 63;
        int v = v0 + vl;
        s_tp[tid] = (v < NV) ? g_tpT[(size_t)rr * NV + v] : 0.f;
    }
    // shape coeffs duplicated
    for (int idx = tid; idx < NBETA * BT; idx += 256) {
        int n = idx >> 5, bt = idx & 31;
        float v = inputs[(size_t)(b0 + bt) * INW + 72 + n];
        *(float2*)(s_shd + idx * 2) = make_float2(v, v);
    }

    // ---- pose GEMM ----
    int mh = wid & 1, nb2 = wid >> 1;
    float acc6[6][4];
#pragma unroll
    for (int t = 0; t < 6; t++)
#pragma unroll
        for (int q = 0; q < 4; q++) acc6[t][q] = 0.f;

    int arow = (mh * 16 + (lane >> 2)) * ASTR + (lane & 3);
    int bcol = nb2 * 48 + (lane >> 2);

    for (int ck = 0; ck < 7; ck++) {
        if (ck + 1 < 7) {
            stage_w(v0, ck + 1, wbase + ((ck + 1) & 1) * (32 * WSTR * 4));
            asm volatile("cp.async.commit_group;" ::: "memory");
            asm volatile("cp.async.wait_group 1;" ::: "memory");
        } else {
            asm volatile("cp.async.wait_group 0;" ::: "memory");
        }
        __syncthreads();
        const float* W = s_W + (ck & 1) * (32 * WSTR);
#pragma unroll
        for (int ks = 0; ks < 4; ks++) {
            int ka = ck * 32 + ks * 8;
            uint32_t a0 = __float_as_uint(s_A[arow + ka]);
            uint32_t a1 = __float_as_uint(s_A[arow + 8 * ASTR + ka]);
            uint32_t a2 = __float_as_uint(s_A[arow + ka + 4]);
            uint32_t a3 = __float_as_uint(s_A[arow + 8 * ASTR + ka + 4]);
            int bro = (ks * 8 + (lane & 3)) * WSTR + bcol;
#pragma unroll
            for (int t = 0; t < 6; t++) {
                uint32_t bb0 = __float_as_uint(W[bro + t * 8]);
                uint32_t bb1 = __float_as_uint(W[bro + 4 * WSTR + t * 8]);
                mma_tf32(acc6[t], a0, a1, a2, a3, bb0, bb1);
            }
        }
        __syncthreads();
    }

    // ---- store pose D to s_vp ----
    {
        int r0 = mh * 16 + (lane >> 2);
        int cb = nb2 * 48 + (lane & 3) * 2;
#pragma unroll
        for (int t = 0; t < 6; t++) {
            *(float2*)(s_vp + r0 * VPSTR + cb + t * 8)       = make_float2(acc6[t][0], acc6[t][1]);
            *(float2*)(s_vp + (r0 + 8) * VPSTR + cb + t * 8) = make_float2(acc6[t][2], acc6[t][3]);
        }
    }
    __syncthreads();

    // ---- v_posed = poseD + template + shape blend ----
    {
        int p = lane;
        int bb0 = wid * 4;
        u64 acc[4][3];
        u64 t2[3];
#pragma unroll
        for (int c = 0; c < 3; c++) t2[c] = *(const u64*)(s_tp + c * 64 + 2 * p);
#pragma unroll
        for (int b = 0; b < 4; b++)
#pragma unroll
            for (int c = 0; c < 3; c++)
                acc[b][c] = add2(*(const u64*)(s_vp + (bb0 + b) * VPSTR + c * 64 + 2 * p), t2[c]);
#pragma unroll
        for (int n = 0; n < NBETA; n++) {
            u64 sd2[3];
#pragma unroll
            for (int c = 0; c < 3; c++)
                sd2[c] = *(const u64*)(s_sd + (n * 3 + c) * 64 + 2 * p);
#pragma unroll
            for (int b = 0; b < 4; b++) {
                u64 sh2 = *(const u64*)(s_shd + (n * 32 + bb0 + b) * 2);
#pragma unroll
                for (int c = 0; c < 3; c++)
                    acc[b][c] = ffma2(sh2, sd2[c], acc[b][c]);
            }
        }
#pragma unroll
        for (int b = 0; b < 4; b++)
#pragma unroll
            for (int c = 0; c < 3; c++)
                *(u64*)(s_vp + (bb0 + b) * VPSTR + c * 64 + 2 * lane) = acc[b][c];
    }
    __syncthreads();

    // ---- LBS via tensor cores ----
    uint32_t afr[4][3][4];
#pragma unroll
    for (int mt = 0; mt < 4; mt++)
#pragma unroll
        for (int ks = 0; ks < 3; ks++) {
            int ar = (mt * 16 + (lane >> 2)) * LBS_STR + ks * 8 + (lane & 3);
            afr[mt][ks][0] = __float_as_uint(s_lb[ar]);
            afr[mt][ks][1] = __float_as_uint(s_lb[ar + 8 * LBS_STR]);
            afr[mt][ks][2] = __float_as_uint(s_lb[ar + 4]);
            afr[mt][ks][3] = __float_as_uint(s_lb[ar + 8 * LBS_STR + 4]);
        }

    int p = lane;
    int v1 = v0 + 2 * p;

    for (int ph = 0; ph < 2; ph++) {
#pragma unroll
        for (int lb = 0; lb < 2; lb++) {
            int lbat = ph * 16 + wid * 2 + lb;
            const float* B = s_rb + lbat * RELB_STR;
            float la[4][2][4];
#pragma unroll
            for (int mt = 0; mt < 4; mt++)
#pragma unroll
                for (int nb = 0; nb < 2; nb++)
#pragma unroll
                    for (int q = 0; q < 4; q++) la[mt][nb][q] = 0.f;
#pragma unroll
            for (int ks = 0; ks < 3; ks++) {
#pragma unroll
                for (int nb = 0; nb < 2; nb++) {
                    int bro = (ks * 8 + (lane & 3)) * 16 + nb * 8 + (lane >> 2);
                    uint32_t bb0 = __float_as_uint(B[bro]);
                    uint32_t bb1 = __float_as_uint(B[bro + 64]);
#pragma unroll
                    for (int mt = 0; mt < 4; mt++)
                        mma_tf32(la[mt][nb], afr[mt][ks][0], afr[mt][ks][1],
                                 afr[mt][ks][2], afr[mt][ks][3], bb0, bb1);
                }
            }
            float* Ts = s_T + (wid * 2 + lb) * TSLOT;
            int r0 = (lane >> 2);
            int c0 = 2 * (lane & 3);
#pragma unroll
            for (int mt = 0; mt < 4; mt++)
#pragma unroll
                for (int nb = 0; nb < 2; nb++) {
                    int n0 = nb * 8 + c0;
                    int rr = mt * 16 + r0;
                    Ts[n0 * TSTR + rr]           = la[mt][nb][0];
                    Ts[(n0 + 1) * TSTR + rr]     = la[mt][nb][1];
                    Ts[n0 * TSTR + rr + 8]       = la[mt][nb][2];
                    Ts[(n0 + 1) * TSTR + rr + 8] = la[mt][nb][3];
                }
        }
        __syncwarp();
        // epilogue: apply T, write gmem, store tf32 verts back to s_vp
#pragma unroll
        for (int lb = 0; lb < 2; lb++) {
            int lbat = ph * 16 + wid * 2 + lb;
            const float* Ts = s_T + (wid * 2 + lb) * TSLOT;
            u64 x2 = *(const u64*)(s_vp + lbat * VPSTR + 2 * p);
            u64 y2 = *(const u64*)(s_vp + lbat * VPSTR + 64 + 2 * p);
            u64 z2 = *(const u64*)(s_vp + lbat * VPSTR + 128 + 2 * p);
            u64 T0 = *(const u64*)(Ts + 0 * TSTR + 2 * p);
            u64 T1 = *(const u64*)(Ts + 1 * TSTR + 2 * p);
            u64 T2 = *(const u64*)(Ts + 2 * TSTR + 2 * p);
            u64 T3 = *(const u64*)(Ts + 3 * TSTR + 2 * p);
            u64 ox = ffma2(T0, x2, ffma2(T1, y2, ffma2(T2, z2, T3)));
            T0 = *(const u64*)(Ts + 4 * TSTR + 2 * p);
            T1 = *(const u64*)(Ts + 5 * TSTR + 2 * p);
            T2 = *(const u64*)(Ts + 6 * TSTR + 2 * p);
            T3 = *(const u64*)(Ts + 7 * TSTR + 2 * p);
            u64 oy = ffma2(T0, x2, ffma2(T1, y2, ffma2(T2, z2, T3)));
            T0 = *(const u64*)(Ts + 8 * TSTR + 2 * p);
            T1 = *(const u64*)(Ts + 9 * TSTR + 2 * p);
            T2 = *(const u64*)(Ts + 10 * TSTR + 2 * p);
            T3 = *(const u64*)(Ts + 11 * TSTR + 2 * p);
            u64 oz = ffma2(T0, x2, ffma2(T1, y2, ffma2(T2, z2, T3)));
            float xa, xb, ya, yb, za, zb;
            unpk(ox, xa, xb); unpk(oy, ya, yb); unpk(oz, za, zb);
            if (v1 < NV) {
                float* d = outV + ((size_t)(b0 + lbat) * NV + v1) * 3;
                *(float2*)(d)     = make_float2(xa, ya);
                *(float2*)(d + 2) = make_float2(za, xb);
                *(float2*)(d + 4) = make_float2(yb, zb);
            }
            // tf32 final verts -> s_vp (A operand for joint GEMM)
            *(u64*)(s_vp + lbat * VPSTR + 2 * p)       = pack2(to_tf32(xa), to_tf32(xb));
            *(u64*)(s_vp + lbat * VPSTR + 64 + 2 * p)  = pack2(to_tf32(ya), to_tf32(yb));
            *(u64*)(s_vp + lbat * VPSTR + 128 + 2 * p) = pack2(to_tf32(za), to_tf32(zb));
        }
        __syncwarp();
    }
    __syncthreads();

    // ---- fused joints: C_c[32x24] = V_c[32x64] @ JR[64x24], atomicAdd ----
    if (wid < 6) {
        int c = wid >> 1;        // channel 0..2
        int mhj = wid & 1;       // batch half
        float jacc[3][4];
#pragma unroll
        for (int nt = 0; nt < 3; nt++)
#pragma unroll
            for (int q = 0; q < 4; q++) jacc[nt][q] = 0.f;

#pragma unroll
        for (int ks = 0; ks < 8; ks++) {
            int kc = ks * 8 + (lane & 3);
            int ab = (mhj * 16 + (lane >> 2)) * VPSTR + c * 64;
            uint32_t a0 = __float_as_uint(s_vp[ab + kc]);
            uint32_t a1 = __float_as_uint(s_vp[ab + 8 * VPSTR + kc]);
            uint32_t a2 = __float_as_uint(s_vp[ab + kc + 4]);
            uint32_t a3 = __float_as_uint(s_vp[ab + 8 * VPSTR + kc + 4]);
#pragma unroll
            for (int nt = 0; nt < 3; nt++) {
                int bro = kc * JSTR + nt * 8 + (lane >> 2);
                uint32_t bb0 = __float_as_uint(s_jr[bro]);
                uint32_t bb1 = __float_as_uint(s_jr[bro + 4 * JSTR]);
                mma_tf32(jacc[nt], a0, a1, a2, a3, bb0, bb1);
            }
        }
        int r0 = lane >> 2, c0 = 2 * (lane & 3);
#pragma unroll
        for (int nt = 0; nt < 3; nt++) {
#pragma unroll
            for (int q = 0; q < 4; q++) {
                int n = nt * 8 + c0 + (q & 1);
                int row = mhj * 16 + r0 + ((q >> 1) << 3);
                if (n < NK)
                    atomicAdd(&outJ[(size_t)(b0 + row) * (NK * 3) + n * 3 + c], jacc[nt][q]);
            }
        }
    }
}

// =====================================================================
extern "C" void kernel_launch(void* const* d_in, const int* in_sizes, int n_in,
                              void* d_out, int out_size)
{
    const float* inputs = (const float*)d_in[0];
    const float* vtempl = (const float*)d_in[1];
    const float* sdirs  = (const float*)d_in[2];
    const float* jreg24 = (const float*)d_in[3];
    const float* pdirs  = (const float*)d_in[4];
    const float* lbsw   = (const float*)d_in[5];
    const float* jreg19 = (const float*)d_in[6];

    float* out   = (float*)d_out;
    float* outV  = out;
    float* outJ  = outV + (size_t)BN * NV * 3;
    float* outRs = outJ + (size_t)BN * NK * 3;

    size_t k2_smem = (size_t)SMEM_FLOATS * sizeof(float); // 180480 B
    cudaFuncSetAttribute(k2_main, cudaFuncAttributeMaxDynamicSharedMemorySize, (int)k2_smem);

    k0a_jointdirs<<<NJ * 3, 256>>>(vtempl, sdirs, jreg24);
    k0w_build<<<KTOT * 3, 256>>>(pdirs);
    k0t1b_planes<<<NBETA * 3 + 3, 256>>>(sdirs, vtempl);
    k0z_zero<<<(BN * NK * 3 + 255) / 256, 256>>>(outJ);
    k1_batchprep<<<BN, 128>>>(inputs, outRs);
    dim3 g2((NV + VT2 - 1) / VT2, BN / BT);
    k2_main<<<g2, 256, k2_smem>>>(inputs, lbsw, jreg19, outV, outJ);
}